// round 3
// baseline (speedup 1.0000x reference)
#include <cuda_runtime.h>
#include <math.h>

#define Bb 4
#define Cc 64
#define Hh 256
#define Ww 256
#define PP (Hh*Ww)          // 65536
#define CH 32

// ---------------- scratch (device globals; no runtime allocs allowed) ----------
__device__ float g_t0[Bb*Cc*PP];       // conv1x1-in output
__device__ float g_dir[4][Bb*Cc*PP];   // 0=up 1=right 2=down 3=left
__device__ float g_t2[Bb*Cc*PP];       // wD2 conv output
__device__ float g_a1[Bb*CH*PP];
__device__ float g_a2[Bb*CH*PP];

// ---------------- packed fp32x2 FMA (2x FFMA rate on sm_103a) ------------------
__device__ __forceinline__ float2 ffma2(float2 a, float2 b, float2 c) {
    unsigned long long ua = *reinterpret_cast<unsigned long long*>(&a);
    unsigned long long ub = *reinterpret_cast<unsigned long long*>(&b);
    unsigned long long uc = *reinterpret_cast<unsigned long long*>(&c);
    unsigned long long ud;
    asm("fma.rn.f32x2 %0, %1, %2, %3;" : "=l"(ud) : "l"(ua), "l"(ub), "l"(uc));
    return *reinterpret_cast<float2*>(&ud);
}

// ================================================================================
// K1: out = w_in[64x64] @ x    (per pixel), NCHW.
// Block: 256 thr, tile = 64 out-ch x 64 positions. o = tid>>2, pgb = tid&3.
// ================================================================================
__global__ __launch_bounds__(256)
void k_conv_in(const float* __restrict__ x, const float* __restrict__ w_in) {
    __shared__ __align__(16) float ws[64*64];   // ws[i*64+o] = w_in[o,i]
    __shared__ __align__(16) float xs[64*64];   // xs[i*64+p]
    int tid = threadIdx.x;
    int blk = blockIdx.x;                 // 4096 blocks
    int b  = blk >> 10;
    int p0 = (blk & 1023) * 64;

    for (int t = tid; t < 4096; t += 256) {
        int o = t & 63, i = t >> 6;
        ws[t] = w_in[o*64 + i];
    }
    for (int t = tid; t < 4096; t += 256) {
        int i = t >> 6, p = t & 63;
        xs[t] = x[(b*64 + i)*PP + p0 + p];
    }
    __syncthreads();

    int o = tid >> 2, pgb = tid & 3;
    float2 acc[8];
    #pragma unroll
    for (int k = 0; k < 8; k++) acc[k] = make_float2(0.f, 0.f);

    #pragma unroll 4
    for (int i = 0; i < 64; i++) {
        float wv = ws[i*64 + o];
        float2 w2 = make_float2(wv, wv);
        #pragma unroll
        for (int k = 0; k < 4; k++) {
            float4 xv = *(const float4*)&xs[i*64 + (pgb + 4*k)*4];
            acc[2*k]   = ffma2(w2, make_float2(xv.x, xv.y), acc[2*k]);
            acc[2*k+1] = ffma2(w2, make_float2(xv.z, xv.w), acc[2*k+1]);
        }
    }
    float* dst = g_t0 + (b*64 + o)*PP + p0;
    #pragma unroll
    for (int k = 0; k < 4; k++) {
        float4 v = make_float4(acc[2*k].x, acc[2*k].y, acc[2*k+1].x, acc[2*k+1].y);
        *(float4*)&dst[(pgb + 4*k)*4] = v;
    }
}

// ================================================================================
// K2v: vertical IRNN scans. blockIdx.x = b*64+c, blockIdx.y: 0=down(fwd) 1=up(rev)
// thread = one w-column; coalesced loads/stores; prefetch-1 on the x stream.
// ================================================================================
__global__ __launch_bounds__(256)
void k_scan_v(const float* __restrict__ w_up, const float* __restrict__ b_up,
              const float* __restrict__ w_down, const float* __restrict__ b_down) {
    int bc = blockIdx.x;
    int c  = bc & 63;
    int up = blockIdx.y;
    int w  = threadIdx.x;
    const float* src = g_t0 + (size_t)bc*PP;
    float* dst = (up ? g_dir[0] : g_dir[2]) + (size_t)bc*PP;
    float wc = up ? w_up[c] : w_down[c];
    float bv = up ? b_up[c] : b_down[c];
    float h = 0.f;
    if (!up) {
        float v = src[w];
        #pragma unroll 4
        for (int y = 0; y < Hh; y++) {
            float vn = (y < Hh-1) ? src[(y+1)*Ww + w] : 0.f;
            h = fmaxf(fmaf(wc, h, v + bv), 0.f);
            dst[y*Ww + w] = h;
            v = vn;
        }
    } else {
        float v = src[(Hh-1)*Ww + w];
        #pragma unroll 4
        for (int y = Hh-1; y >= 0; y--) {
            float vn = (y > 0) ? src[(y-1)*Ww + w] : 0.f;
            h = fmaxf(fmaf(wc, h, v + bv), 0.f);
            dst[y*Ww + w] = h;
            v = vn;
        }
    }
}

// ================================================================================
// K2h: horizontal IRNN scans via warp-owned 32x32 smem transpose tiles.
// blockIdx.x = b*64+c, blockIdx.y: 0=right(fwd) 1=left(rev). 8 warps x 32 rows.
// ================================================================================
__global__ __launch_bounds__(256)
void k_scan_h(const float* __restrict__ w_right, const float* __restrict__ b_right,
              const float* __restrict__ w_left, const float* __restrict__ b_left) {
    __shared__ float s[8][32][33];
    int bc = blockIdx.x;
    int c  = bc & 63;
    int lft = blockIdx.y;
    int lane = threadIdx.x & 31, warp = threadIdx.x >> 5;
    const float* src = g_t0 + (size_t)bc*PP;
    float* dst = (lft ? g_dir[3] : g_dir[1]) + (size_t)bc*PP;
    float wc = lft ? w_left[c] : w_right[c];
    float bv = lft ? b_left[c] : b_right[c];
    int row0 = warp * 32;
    float h = 0.f;
    for (int ch = 0; ch < 8; ch++) {
        int c0 = lft ? (224 - ch*32) : ch*32;
        #pragma unroll
        for (int r = 0; r < 32; r++)
            s[warp][r][lane] = src[(row0 + r)*Ww + c0 + lane];
        __syncwarp();
        if (!lft) {
            #pragma unroll
            for (int j = 0; j < 32; j++) {
                float v = s[warp][lane][j];
                h = fmaxf(fmaf(wc, h, v + bv), 0.f);
                s[warp][lane][j] = h;
            }
        } else {
            #pragma unroll
            for (int j = 31; j >= 0; j--) {
                float v = s[warp][lane][j];
                h = fmaxf(fmaf(wc, h, v + bv), 0.f);
                s[warp][lane][j] = h;
            }
        }
        __syncwarp();
        #pragma unroll
        for (int r = 0; r < 32; r++)
            dst[(row0 + r)*Ww + c0 + lane] = s[warp][r][lane];
        __syncwarp();
    }
}

// ================================================================================
// K3: out2 = relu( wD2[64x256] @ cat ), cat = [up,right,down,left].
// Same tiling as K1, looping over the 4 direction chunks.
// ================================================================================
__global__ __launch_bounds__(256)
void k_convD2(const float* __restrict__ wD2) {
    __shared__ __align__(16) float ws[64*64];
    __shared__ __align__(16) float xs[64*64];
    int tid = threadIdx.x;
    int blk = blockIdx.x;
    int b  = blk >> 10;
    int p0 = (blk & 1023) * 64;
    int o = tid >> 2, pgb = tid & 3;

    float2 acc[8];
    #pragma unroll
    for (int k = 0; k < 8; k++) acc[k] = make_float2(0.f, 0.f);

    for (int d = 0; d < 4; d++) {
        __syncthreads();
        for (int t = tid; t < 4096; t += 256) {
            int oo = t & 63, i = t >> 6;
            ws[t] = wD2[oo*256 + d*64 + i];
        }
        const float* src = g_dir[d];
        for (int t = tid; t < 4096; t += 256) {
            int i = t >> 6, p = t & 63;
            xs[t] = src[(b*64 + i)*PP + p0 + p];
        }
        __syncthreads();
        #pragma unroll 4
        for (int i = 0; i < 64; i++) {
            float wv = ws[i*64 + o];
            float2 w2 = make_float2(wv, wv);
            #pragma unroll
            for (int k = 0; k < 4; k++) {
                float4 xv = *(const float4*)&xs[i*64 + (pgb + 4*k)*4];
                acc[2*k]   = ffma2(w2, make_float2(xv.x, xv.y), acc[2*k]);
                acc[2*k+1] = ffma2(w2, make_float2(xv.z, xv.w), acc[2*k+1]);
            }
        }
    }
    float* dst = g_t2 + (b*64 + o)*PP + p0;
    #pragma unroll
    for (int k = 0; k < 4; k++) {
        float4 v = make_float4(fmaxf(acc[2*k].x, 0.f),   fmaxf(acc[2*k].y, 0.f),
                               fmaxf(acc[2*k+1].x, 0.f), fmaxf(acc[2*k+1].y, 0.f));
        *(float4*)&dst[(pgb + 4*k)*4] = v;
    }
}

// ================================================================================
// K4/K5: conv3x3 SAME + relu, OC=32, IC templated (64 then 32), ic-chunked by 16.
// Block = 256 thr = 32x8 output pixels; each thread computes all 32 oc as 16 f32x2.
// Weight LDS.64 are warp-uniform -> broadcast; issue mix ~ LDS/FFMA2 alternating
// which exactly matches FFMA2 rt=2 -> FMA-rate-bound.
// ================================================================================
template<int IC, int LAYER>
__global__ __launch_bounds__(256)
void k_conv3(const float* __restrict__ wg, const float* __restrict__ bias) {
    constexpr int OC = 32;
    constexpr int CHU = 16;
    __shared__ __align__(16) float wsm[CHU*9*OC];     // [(icl*9+k)*32 + oc]
    __shared__ float in_s[CHU][10][36];

    const float* src = (LAYER == 0) ? g_t2 : g_a1;
    float*       dst = (LAYER == 0) ? g_a1 : g_a2;

    int tid = threadIdx.x;
    int tx = tid & 31, ty = tid >> 5;                  // 32 x 8 pixels
    int blk = blockIdx.x;                              // 4 * 32 * 8 = 1024
    int b  = blk >> 8;
    int t  = blk & 255;
    int ty0 = (t >> 3) * 8;
    int tx0 = (t & 7) * 32;
    const float* sb = src + (size_t)b*IC*PP;

    float2 acc[16];
    #pragma unroll
    for (int k = 0; k < 16; k++) acc[k] = make_float2(0.f, 0.f);

    for (int ic0 = 0; ic0 < IC; ic0 += CHU) {
        __syncthreads();
        for (int tt = tid; tt < CHU*9*OC; tt += 256) {
            int oc = tt & 31;
            int rest = tt >> 5;
            int k = rest % 9, icl = rest / 9;
            wsm[tt] = wg[((oc*IC) + ic0 + icl)*9 + k];
        }
        for (int tt = tid; tt < CHU*10*34; tt += 256) {
            int col = tt % 34;
            int rr  = (tt / 34) % 10;
            int icl = tt / 340;
            int gy = ty0 + rr - 1, gx = tx0 + col - 1;
            float v = 0.f;
            if (gy >= 0 && gy < Hh && gx >= 0 && gx < Ww)
                v = sb[(ic0 + icl)*PP + gy*Ww + gx];
            in_s[icl][rr][col] = v;
        }
        __syncthreads();

        for (int icl = 0; icl < CHU; icl++) {
            float xv[9];
            #pragma unroll
            for (int dy = 0; dy < 3; dy++)
                #pragma unroll
                for (int dx = 0; dx < 3; dx++)
                    xv[dy*3 + dx] = in_s[icl][ty + dy][tx + dx];
            const float2* w2 = (const float2*)&wsm[icl*9*OC];
            #pragma unroll
            for (int k = 0; k < 9; k++) {
                float2 x2 = make_float2(xv[k], xv[k]);
                #pragma unroll
                for (int op = 0; op < 16; op++)
                    acc[op] = ffma2(w2[k*16 + op], x2, acc[op]);
            }
        }
    }
    int py = ty0 + ty, px = tx0 + tx;
    #pragma unroll
    for (int op = 0; op < 16; op++) {
        float a0 = fmaxf(acc[op].x + bias[2*op],     0.f);
        float a1 = fmaxf(acc[op].y + bias[2*op + 1], 0.f);
        dst[((size_t)b*OC + 2*op    )*PP + py*Ww + px] = a0;
        dst[((size_t)b*OC + 2*op + 1)*PP + py*Ww + px] = a1;
    }
}

// ================================================================================
// K6: a = a3w @ g_a2 + a3b ; weight = sigmoid(a) ; out = relu(x * weight)
// thread = 4 consecutive pixels (float4), all 64 channels.
// ================================================================================
__global__ __launch_bounds__(256)
void k_final(const float* __restrict__ x, const float* __restrict__ a3w,
             const float* __restrict__ a3b, float* __restrict__ out) {
    int idx = blockIdx.x * 256 + threadIdx.x;       // 65536 float4 groups
    int b  = idx >> 14;
    int p4 = (idx & 16383) * 4;
    float4 acc = make_float4(0.f, 0.f, 0.f, 0.f);
    #pragma unroll 8
    for (int ic = 0; ic < 32; ic++) {
        float wv = a3w[ic];
        float4 v = *(const float4*)&g_a2[((size_t)b*32 + ic)*PP + p4];
        acc.x = fmaf(wv, v.x, acc.x);
        acc.y = fmaf(wv, v.y, acc.y);
        acc.z = fmaf(wv, v.z, acc.z);
        acc.w = fmaf(wv, v.w, acc.w);
    }
    float bb = a3b[0];
    float4 wt;
    wt.x = 1.f / (1.f + expf(-(acc.x + bb)));
    wt.y = 1.f / (1.f + expf(-(acc.y + bb)));
    wt.z = 1.f / (1.f + expf(-(acc.z + bb)));
    wt.w = 1.f / (1.f + expf(-(acc.w + bb)));
    #pragma unroll 4
    for (int c = 0; c < 64; c++) {
        float4 xv = *(const float4*)&x[((size_t)b*64 + c)*PP + p4];
        float4 o;
        o.x = fmaxf(xv.x * wt.x, 0.f);
        o.y = fmaxf(xv.y * wt.y, 0.f);
        o.z = fmaxf(xv.z * wt.z, 0.f);
        o.w = fmaxf(xv.w * wt.w, 0.f);
        *(float4*)&out[((size_t)b*64 + c)*PP + p4] = o;
    }
}

// ================================================================================
extern "C" void kernel_launch(void* const* d_in, const int* in_sizes, int n_in,
                              void* d_out, int out_size) {
    const float* x       = (const float*)d_in[0];
    const float* w_in    = (const float*)d_in[1];
    const float* w_up    = (const float*)d_in[2];
    const float* b_up    = (const float*)d_in[3];
    const float* w_right = (const float*)d_in[4];
    const float* b_right = (const float*)d_in[5];
    const float* w_down  = (const float*)d_in[6];
    const float* b_down  = (const float*)d_in[7];
    const float* w_left  = (const float*)d_in[8];
    const float* b_left  = (const float*)d_in[9];
    const float* wD2     = (const float*)d_in[10];
    const float* a1w     = (const float*)d_in[11];
    const float* a1b     = (const float*)d_in[12];
    const float* a2w     = (const float*)d_in[13];
    const float* a2b     = (const float*)d_in[14];
    const float* a3w     = (const float*)d_in[15];
    const float* a3b     = (const float*)d_in[16];
    float* out = (float*)d_out;

    k_conv_in<<<4096, 256>>>(x, w_in);
    dim3 gscan(Bb*Cc, 2);
    k_scan_v<<<gscan, 256>>>(w_up, b_up, w_down, b_down);
    k_scan_h<<<gscan, 256>>>(w_right, b_right, w_left, b_left);
    k_convD2<<<4096, 256>>>(wD2);
    k_conv3<64, 0><<<1024, 256>>>(a1w, a1b);
    k_conv3<32, 1><<<1024, 256>>>(a2w, a2b);
    k_final<<<256, 256>>>(x, a3w, a3b, out);
}

// round 4
// speedup vs baseline: 1.5749x; 1.5749x over previous
#include <cuda_runtime.h>
#include <math.h>

#define Bb 4
#define Cc 64
#define Hh 256
#define Ww 256
#define PP (Hh*Ww)          // 65536
#define CH 32

// ---------------- scratch (device globals; no runtime allocs allowed) ----------
__device__ float g_t0[Bb*Cc*PP];       // conv1x1-in output
__device__ float g_dir[4][Bb*Cc*PP];   // 0=up 1=right 2=down 3=left
__device__ float g_t2[Bb*Cc*PP];       // wD2 conv output
__device__ float g_a1[Bb*CH*PP];
__device__ float g_a2[Bb*CH*PP];

// ---------------- packed fp32x2 FMA (2x FFMA rate on sm_103a) ------------------
__device__ __forceinline__ float2 ffma2(float2 a, float2 b, float2 c) {
    unsigned long long ua = *reinterpret_cast<unsigned long long*>(&a);
    unsigned long long ub = *reinterpret_cast<unsigned long long*>(&b);
    unsigned long long uc = *reinterpret_cast<unsigned long long*>(&c);
    unsigned long long ud;
    asm("fma.rn.f32x2 %0, %1, %2, %3;" : "=l"(ud) : "l"(ua), "l"(ub), "l"(uc));
    return *reinterpret_cast<float2*>(&ud);
}

// ================================================================================
// K1: out = w_in[64x64] @ x  (per pixel), NCHW. Register outer-product tiling:
// block tile 64oc x 128px, thread = 8oc x 4px. Warp-uniform weight LDS (broadcast)
// + 1 LDS.128 of x per K-step for 16 FFMA2 -> fma-pipe bound.
// ================================================================================
__global__ __launch_bounds__(256)
void k_conv_in(const float* __restrict__ x, const float* __restrict__ w_in) {
    __shared__ __align__(16) float ws[64*64];    // ws[i*64+o]
    __shared__ __align__(16) float xs[64*128];   // xs[i*128+p]
    int tid = threadIdx.x;
    int blk = blockIdx.x;                 // 2048 blocks
    int b   = blk >> 9;
    int p0g = (blk & 511) * 128;
    int o0  = (tid >> 5) * 8;             // warp-uniform
    int p0  = (tid & 31) * 4;

    for (int t = tid; t < 4096; t += 256) {
        int o = t & 63, i = t >> 6;
        ws[t] = w_in[o*64 + i];
    }
    const float* src = x + (size_t)b*64*PP + p0g;
    for (int t = tid; t < 2048; t += 256) {
        int i = t >> 5, p4 = (t & 31) * 4;
        *(float4*)&xs[i*128 + p4] = *(const float4*)&src[(size_t)i*PP + p4];
    }
    __syncthreads();

    float2 acc[8][2];
    #pragma unroll
    for (int oo = 0; oo < 8; oo++) { acc[oo][0] = make_float2(0.f,0.f); acc[oo][1] = make_float2(0.f,0.f); }

    #pragma unroll 2
    for (int i = 0; i < 64; i++) {
        float4 w0 = *(const float4*)&ws[i*64 + o0];
        float4 w1 = *(const float4*)&ws[i*64 + o0 + 4];
        float4 xv = *(const float4*)&xs[i*128 + p0];
        float2 x01 = make_float2(xv.x, xv.y);
        float2 x23 = make_float2(xv.z, xv.w);
        float wv[8] = {w0.x,w0.y,w0.z,w0.w,w1.x,w1.y,w1.z,w1.w};
        #pragma unroll
        for (int oo = 0; oo < 8; oo++) {
            float2 w2 = make_float2(wv[oo], wv[oo]);
            acc[oo][0] = ffma2(w2, x01, acc[oo][0]);
            acc[oo][1] = ffma2(w2, x23, acc[oo][1]);
        }
    }
    float* dst = g_t0 + (size_t)b*64*PP + p0g;
    #pragma unroll
    for (int oo = 0; oo < 8; oo++) {
        float4 v = make_float4(acc[oo][0].x, acc[oo][0].y, acc[oo][1].x, acc[oo][1].y);
        *(float4*)&dst[(size_t)(o0+oo)*PP + p0] = v;
    }
}

// ================================================================================
// K2v: vertical IRNN scans. blockIdx.x = b*64+c, blockIdx.y: 0=down(fwd) 1=up(rev)
// ================================================================================
__global__ __launch_bounds__(256)
void k_scan_v(const float* __restrict__ w_up, const float* __restrict__ b_up,
              const float* __restrict__ w_down, const float* __restrict__ b_down) {
    int bc = blockIdx.x;
    int c  = bc & 63;
    int up = blockIdx.y;
    int w  = threadIdx.x;
    const float* src = g_t0 + (size_t)bc*PP;
    float* dst = (up ? g_dir[0] : g_dir[2]) + (size_t)bc*PP;
    float wc = up ? w_up[c] : w_down[c];
    float bv = up ? b_up[c] : b_down[c];
    float h = 0.f;
    if (!up) {
        float v = src[w];
        #pragma unroll 4
        for (int y = 0; y < Hh; y++) {
            float vn = (y < Hh-1) ? src[(y+1)*Ww + w] : 0.f;
            h = fmaxf(fmaf(wc, h, v + bv), 0.f);
            dst[y*Ww + w] = h;
            v = vn;
        }
    } else {
        float v = src[(Hh-1)*Ww + w];
        #pragma unroll 4
        for (int y = Hh-1; y >= 0; y--) {
            float vn = (y > 0) ? src[(y-1)*Ww + w] : 0.f;
            h = fmaxf(fmaf(wc, h, v + bv), 0.f);
            dst[y*Ww + w] = h;
            v = vn;
        }
    }
}

// ================================================================================
// K2h: horizontal IRNN scans via warp-owned 32x32 smem transpose tiles.
// ================================================================================
__global__ __launch_bounds__(256)
void k_scan_h(const float* __restrict__ w_right, const float* __restrict__ b_right,
              const float* __restrict__ w_left, const float* __restrict__ b_left) {
    __shared__ float s[8][32][33];
    int bc = blockIdx.x;
    int c  = bc & 63;
    int lft = blockIdx.y;
    int lane = threadIdx.x & 31, warp = threadIdx.x >> 5;
    const float* src = g_t0 + (size_t)bc*PP;
    float* dst = (lft ? g_dir[3] : g_dir[1]) + (size_t)bc*PP;
    float wc = lft ? w_left[c] : w_right[c];
    float bv = lft ? b_left[c] : b_right[c];
    int row0 = warp * 32;
    float h = 0.f;
    for (int ch = 0; ch < 8; ch++) {
        int c0 = lft ? (224 - ch*32) : ch*32;
        #pragma unroll
        for (int r = 0; r < 32; r++)
            s[warp][r][lane] = src[(row0 + r)*Ww + c0 + lane];
        __syncwarp();
        if (!lft) {
            #pragma unroll
            for (int j = 0; j < 32; j++) {
                float v = s[warp][lane][j];
                h = fmaxf(fmaf(wc, h, v + bv), 0.f);
                s[warp][lane][j] = h;
            }
        } else {
            #pragma unroll
            for (int j = 31; j >= 0; j--) {
                float v = s[warp][lane][j];
                h = fmaxf(fmaf(wc, h, v + bv), 0.f);
                s[warp][lane][j] = h;
            }
        }
        __syncwarp();
        #pragma unroll
        for (int r = 0; r < 32; r++)
            dst[(row0 + r)*Ww + c0 + lane] = s[warp][r][lane];
        __syncwarp();
    }
}

// ================================================================================
// K3: out2 = relu( wD2[64x256] @ cat ). Same register outer-product tiling as K1,
// looping over the 4 direction chunks. Tile 64oc x 128px, thread 8oc x 4px.
// ================================================================================
__global__ __launch_bounds__(256)
void k_convD2(const float* __restrict__ wD2) {
    __shared__ __align__(16) float ws[64*64];
    __shared__ __align__(16) float xs[64*128];
    int tid = threadIdx.x;
    int blk = blockIdx.x;                 // 2048 blocks
    int b   = blk >> 9;
    int p0g = (blk & 511) * 128;
    int o0  = (tid >> 5) * 8;
    int p0  = (tid & 31) * 4;

    float2 acc[8][2];
    #pragma unroll
    for (int oo = 0; oo < 8; oo++) { acc[oo][0] = make_float2(0.f,0.f); acc[oo][1] = make_float2(0.f,0.f); }

    for (int d = 0; d < 4; d++) {
        __syncthreads();
        for (int t = tid; t < 4096; t += 256) {
            int o = t & 63, i = t >> 6;
            ws[t] = wD2[o*256 + d*64 + i];
        }
        const float* src = g_dir[d] + (size_t)b*64*PP + p0g;
        for (int t = tid; t < 2048; t += 256) {
            int i = t >> 5, p4 = (t & 31) * 4;
            *(float4*)&xs[i*128 + p4] = *(const float4*)&src[(size_t)i*PP + p4];
        }
        __syncthreads();
        #pragma unroll 2
        for (int i = 0; i < 64; i++) {
            float4 w0 = *(const float4*)&ws[i*64 + o0];
            float4 w1 = *(const float4*)&ws[i*64 + o0 + 4];
            float4 xv = *(const float4*)&xs[i*128 + p0];
            float2 x01 = make_float2(xv.x, xv.y);
            float2 x23 = make_float2(xv.z, xv.w);
            float wv[8] = {w0.x,w0.y,w0.z,w0.w,w1.x,w1.y,w1.z,w1.w};
            #pragma unroll
            for (int oo = 0; oo < 8; oo++) {
                float2 w2 = make_float2(wv[oo], wv[oo]);
                acc[oo][0] = ffma2(w2, x01, acc[oo][0]);
                acc[oo][1] = ffma2(w2, x23, acc[oo][1]);
            }
        }
    }
    float* dst = g_t2 + (size_t)b*64*PP + p0g;
    #pragma unroll
    for (int oo = 0; oo < 8; oo++) {
        float4 v = make_float4(fmaxf(acc[oo][0].x, 0.f), fmaxf(acc[oo][0].y, 0.f),
                               fmaxf(acc[oo][1].x, 0.f), fmaxf(acc[oo][1].y, 0.f));
        *(float4*)&dst[(size_t)(o0+oo)*PP + p0] = v;
    }
}

// ================================================================================
// K4/K5: conv3x3 SAME + relu, OC=32, IC templated. CHU=8 ic-chunks.
// Block = 256 thr = 16x16 threads; each thread: 2 adjacent pixels x all 32 oc.
// Per ic: 12 x-values held in regs across the 9 taps; weights via LDS.128
// (warp-uniform broadcast). ~84 LDS vs 288 FFMA2 per ic -> fma-bound.
// ================================================================================
template<int IC, int LAYER>
__global__ __launch_bounds__(256)
void k_conv3(const float* __restrict__ wg, const float* __restrict__ bias) {
    constexpr int OC = 32;
    constexpr int CHU = 8;
    __shared__ __align__(16) float wsm[CHU*9*OC];     // [(icl*9+k)*32 + oc]  9KB
    __shared__ float in_s[CHU][18][36];               // 20.25KB

    const float* src = (LAYER == 0) ? g_t2 : g_a1;
    float*       dst = (LAYER == 0) ? g_a1 : g_a2;

    int tid = threadIdx.x;
    int tx = tid & 15, ty = tid >> 4;                  // 16x16 threads
    int blk = blockIdx.x;                              // 4 * 16 * 8 = 512
    int b   = blk >> 7;
    int t   = blk & 127;
    int ty0 = (t >> 3) * 16;                           // 16 row-tiles of 16
    int tx0 = (t & 7) * 32;                            // 8 col-tiles of 32
    const float* sb = src + (size_t)b*IC*PP;

    float2 acc0[16], acc1[16];                         // px0 / px1, 32 oc each
    #pragma unroll
    for (int op = 0; op < 16; op++) { acc0[op] = make_float2(0.f,0.f); acc1[op] = make_float2(0.f,0.f); }

    for (int ic0 = 0; ic0 < IC; ic0 += CHU) {
        __syncthreads();
        for (int tt = tid; tt < CHU*9*OC; tt += 256) {
            int oc = tt & 31;
            int rest = tt >> 5;
            int k = rest % 9, icl = rest / 9;
            wsm[tt] = wg[((oc*IC) + ic0 + icl)*9 + k];
        }
        for (int tt = tid; tt < CHU*18*34; tt += 256) {
            int col = tt % 34;
            int rr  = (tt / 34) % 18;
            int icl = tt / (34*18);
            int gy = ty0 + rr - 1, gx = tx0 + col - 1;
            float v = 0.f;
            if (gy >= 0 && gy < Hh && gx >= 0 && gx < Ww)
                v = sb[(size_t)(ic0 + icl)*PP + gy*Ww + gx];
            in_s[icl][rr][col] = v;
        }
        __syncthreads();

        for (int icl = 0; icl < CHU; icl++) {
            float xv[3][4];
            #pragma unroll
            for (int dy = 0; dy < 3; dy++)
                #pragma unroll
                for (int dx = 0; dx < 4; dx++)
                    xv[dy][dx] = in_s[icl][ty + dy][2*tx + dx];
            #pragma unroll
            for (int dy = 0; dy < 3; dy++) {
                #pragma unroll
                for (int dx = 0; dx < 3; dx++) {
                    int k = dy*3 + dx;
                    float2 x0 = make_float2(xv[dy][dx],   xv[dy][dx]);
                    float2 x1 = make_float2(xv[dy][dx+1], xv[dy][dx+1]);
                    const float4* w4 = (const float4*)&wsm[(icl*9 + k)*OC];
                    #pragma unroll
                    for (int q = 0; q < 8; q++) {
                        float4 wv = w4[q];                       // warp-uniform LDS.128
                        float2 wa = make_float2(wv.x, wv.y);
                        float2 wb = make_float2(wv.z, wv.w);
                        acc0[2*q]   = ffma2(wa, x0, acc0[2*q]);
                        acc0[2*q+1] = ffma2(wb, x0, acc0[2*q+1]);
                        acc1[2*q]   = ffma2(wa, x1, acc1[2*q]);
                        acc1[2*q+1] = ffma2(wb, x1, acc1[2*q+1]);
                    }
                }
            }
        }
    }
    int py = ty0 + ty, px = tx0 + 2*tx;
    #pragma unroll
    for (int op = 0; op < 16; op++) {
        float ba = bias[2*op], bbv = bias[2*op + 1];
        float2 vA = make_float2(fmaxf(acc0[op].x + ba, 0.f), fmaxf(acc1[op].x + ba, 0.f));   // oc 2op, px0/px1
        float2 vB = make_float2(fmaxf(acc0[op].y + bbv, 0.f), fmaxf(acc1[op].y + bbv, 0.f)); // oc 2op+1
        *(float2*)&dst[((size_t)b*OC + 2*op    )*PP + py*Ww + px] = vA;
        *(float2*)&dst[((size_t)b*OC + 2*op + 1)*PP + py*Ww + px] = vB;
    }
}

// ================================================================================
// K6: a = a3w @ g_a2 + a3b ; weight = sigmoid(a) ; out = relu(x * weight)
// ================================================================================
__global__ __launch_bounds__(256)
void k_final(const float* __restrict__ x, const float* __restrict__ a3w,
             const float* __restrict__ a3b, float* __restrict__ out) {
    int idx = blockIdx.x * 256 + threadIdx.x;       // 65536 float4 groups
    int b  = idx >> 14;
    int p4 = (idx & 16383) * 4;
    float4 acc = make_float4(0.f, 0.f, 0.f, 0.f);
    #pragma unroll 8
    for (int ic = 0; ic < 32; ic++) {
        float wv = a3w[ic];
        float4 v = *(const float4*)&g_a2[((size_t)b*32 + ic)*PP + p4];
        acc.x = fmaf(wv, v.x, acc.x);
        acc.y = fmaf(wv, v.y, acc.y);
        acc.z = fmaf(wv, v.z, acc.z);
        acc.w = fmaf(wv, v.w, acc.w);
    }
    float bb = a3b[0];
    float4 wt;
    wt.x = 1.f / (1.f + expf(-(acc.x + bb)));
    wt.y = 1.f / (1.f + expf(-(acc.y + bb)));
    wt.z = 1.f / (1.f + expf(-(acc.z + bb)));
    wt.w = 1.f / (1.f + expf(-(acc.w + bb)));
    #pragma unroll 4
    for (int c = 0; c < 64; c++) {
        float4 xv = *(const float4*)&x[((size_t)b*64 + c)*PP + p4];
        float4 o;
        o.x = fmaxf(xv.x * wt.x, 0.f);
        o.y = fmaxf(xv.y * wt.y, 0.f);
        o.z = fmaxf(xv.z * wt.z, 0.f);
        o.w = fmaxf(xv.w * wt.w, 0.f);
        *(float4*)&out[((size_t)b*64 + c)*PP + p4] = o;
    }
}

// ================================================================================
extern "C" void kernel_launch(void* const* d_in, const int* in_sizes, int n_in,
                              void* d_out, int out_size) {
    const float* x       = (const float*)d_in[0];
    const float* w_in    = (const float*)d_in[1];
    const float* w_up    = (const float*)d_in[2];
    const float* b_up    = (const float*)d_in[3];
    const float* w_right = (const float*)d_in[4];
    const float* b_right = (const float*)d_in[5];
    const float* w_down  = (const float*)d_in[6];
    const float* b_down  = (const float*)d_in[7];
    const float* w_left  = (const float*)d_in[8];
    const float* b_left  = (const float*)d_in[9];
    const float* wD2     = (const float*)d_in[10];
    const float* a1w     = (const float*)d_in[11];
    const float* a1b     = (const float*)d_in[12];
    const float* a2w     = (const float*)d_in[13];
    const float* a2b     = (const float*)d_in[14];
    const float* a3w     = (const float*)d_in[15];
    const float* a3b     = (const float*)d_in[16];
    float* out = (float*)d_out;

    k_conv_in<<<2048, 256>>>(x, w_in);
    dim3 gscan(Bb*Cc, 2);
    k_scan_v<<<gscan, 256>>>(w_up, b_up, w_down, b_down);
    k_scan_h<<<gscan, 256>>>(w_right, b_right, w_left, b_left);
    k_convD2<<<2048, 256>>>(wD2);
    k_conv3<64, 0><<<512, 256>>>(a1w, a1b);
    k_conv3<32, 1><<<512, 256>>>(a2w, a2b);
    k_final<<<256, 256>>>(x, a3w, a3b, out);
}

// round 6
// speedup vs baseline: 1.5846x; 1.0061x over previous
#include <cuda_runtime.h>
#include <math.h>

#define Bb 4
#define Cc 64
#define Hh 256
#define Ww 256
#define PP (Hh*Ww)          // 65536
#define CH 32

// ---------------- scratch (device globals; no runtime allocs allowed) ----------
__device__ float g_t0[Bb*Cc*PP];       // conv1x1-in output
__device__ float g_dir[4][Bb*Cc*PP];   // 0=up 1=right 2=down 3=left
__device__ float g_t2[Bb*Cc*PP];       // wD2 conv output
__device__ float g_a1[Bb*CH*PP];
__device__ float g_a2[Bb*CH*PP];

// ---------------- packed fp32x2 FMA (2x FFMA rate on sm_103a) ------------------
__device__ __forceinline__ float2 ffma2(float2 a, float2 b, float2 c) {
    unsigned long long ua = *reinterpret_cast<unsigned long long*>(&a);
    unsigned long long ub = *reinterpret_cast<unsigned long long*>(&b);
    unsigned long long uc = *reinterpret_cast<unsigned long long*>(&c);
    unsigned long long ud;
    asm("fma.rn.f32x2 %0, %1, %2, %3;" : "=l"(ud) : "l"(ua), "l"(ub), "l"(uc));
    return *reinterpret_cast<float2*>(&ud);
}

// ================================================================================
// K1: out = w_in[64x64] @ x. Block tile 64oc x 128px, 128 threads,
// thread = 16oc x 4px. Per K-step: 4 broadcast weight LDS.128 + 1 x LDS.128
// for 32 FFMA2 -> crossbar:fma = 1:2 per SM -> fma-pipe bound.
// ================================================================================
__global__ __launch_bounds__(128)
void k_conv_in(const float* __restrict__ x, const float* __restrict__ w_in) {
    __shared__ __align__(16) float ws[64*64];    // ws[i*64+o]  16KB
    __shared__ __align__(16) float xs[64*128];   // xs[i*128+p] 32KB
    int tid = threadIdx.x;
    int blk = blockIdx.x;                 // 2048 blocks
    int b   = blk >> 9;
    int p0g = (blk & 511) * 128;
    int o0  = (tid >> 5) * 16;            // warp-uniform, 4 warps
    int p0  = (tid & 31) * 4;

    for (int t = tid; t < 4096; t += 128) {
        int o = t & 63, i = t >> 6;
        ws[t] = w_in[o*64 + i];
    }
    const float* src = x + (size_t)b*64*PP + p0g;
    for (int t = tid; t < 2048; t += 128) {
        int i = t >> 5, p4 = (t & 31) * 4;
        *(float4*)&xs[i*128 + p4] = *(const float4*)&src[(size_t)i*PP + p4];
    }
    __syncthreads();

    float2 acc[16][2];
    #pragma unroll
    for (int oo = 0; oo < 16; oo++) { acc[oo][0] = make_float2(0.f,0.f); acc[oo][1] = make_float2(0.f,0.f); }

    #pragma unroll 2
    for (int i = 0; i < 64; i++) {
        float4 w0 = *(const float4*)&ws[i*64 + o0];
        float4 w1 = *(const float4*)&ws[i*64 + o0 + 4];
        float4 w2_ = *(const float4*)&ws[i*64 + o0 + 8];
        float4 w3 = *(const float4*)&ws[i*64 + o0 + 12];
        float4 xv = *(const float4*)&xs[i*128 + p0];
        float2 x01 = make_float2(xv.x, xv.y);
        float2 x23 = make_float2(xv.z, xv.w);
        float wv[16] = {w0.x,w0.y,w0.z,w0.w, w1.x,w1.y,w1.z,w1.w,
                        w2_.x,w2_.y,w2_.z,w2_.w, w3.x,w3.y,w3.z,w3.w};
        #pragma unroll
        for (int oo = 0; oo < 16; oo++) {
            float2 w2 = make_float2(wv[oo], wv[oo]);
            acc[oo][0] = ffma2(w2, x01, acc[oo][0]);
            acc[oo][1] = ffma2(w2, x23, acc[oo][1]);
        }
    }
    float* dst = g_t0 + (size_t)b*64*PP + p0g;
    #pragma unroll
    for (int oo = 0; oo < 16; oo++) {
        float4 v = make_float4(acc[oo][0].x, acc[oo][0].y, acc[oo][1].x, acc[oo][1].y);
        *(float4*)&dst[(size_t)(o0+oo)*PP + p0] = v;
    }
}

// ================================================================================
// K2v: vertical IRNN scans. blockIdx.x = b*64+c, blockIdx.y: 0=down(fwd) 1=up(rev)
// ================================================================================
__global__ __launch_bounds__(256)
void k_scan_v(const float* __restrict__ w_up, const float* __restrict__ b_up,
              const float* __restrict__ w_down, const float* __restrict__ b_down) {
    int bc = blockIdx.x;
    int c  = bc & 63;
    int up = blockIdx.y;
    int w  = threadIdx.x;
    const float* src = g_t0 + (size_t)bc*PP;
    float* dst = (up ? g_dir[0] : g_dir[2]) + (size_t)bc*PP;
    float wc = up ? w_up[c] : w_down[c];
    float bv = up ? b_up[c] : b_down[c];
    float h = 0.f;
    if (!up) {
        float v = src[w];
        #pragma unroll 4
        for (int y = 0; y < Hh; y++) {
            float vn = (y < Hh-1) ? src[(y+1)*Ww + w] : 0.f;
            h = fmaxf(fmaf(wc, h, v + bv), 0.f);
            dst[y*Ww + w] = h;
            v = vn;
        }
    } else {
        float v = src[(Hh-1)*Ww + w];
        #pragma unroll 4
        for (int y = Hh-1; y >= 0; y--) {
            float vn = (y > 0) ? src[(y-1)*Ww + w] : 0.f;
            h = fmaxf(fmaf(wc, h, v + bv), 0.f);
            dst[y*Ww + w] = h;
            v = vn;
        }
    }
}

// ================================================================================
// K2h: horizontal IRNN scans via warp-owned 32x32 smem transpose tiles.
// ================================================================================
__global__ __launch_bounds__(256)
void k_scan_h(const float* __restrict__ w_right, const float* __restrict__ b_right,
              const float* __restrict__ w_left, const float* __restrict__ b_left) {
    __shared__ float s[8][32][33];
    int bc = blockIdx.x;
    int c  = bc & 63;
    int lft = blockIdx.y;
    int lane = threadIdx.x & 31, warp = threadIdx.x >> 5;
    const float* src = g_t0 + (size_t)bc*PP;
    float* dst = (lft ? g_dir[3] : g_dir[1]) + (size_t)bc*PP;
    float wc = lft ? w_left[c] : w_right[c];
    float bv = lft ? b_left[c] : b_right[c];
    int row0 = warp * 32;
    float h = 0.f;
    for (int ch = 0; ch < 8; ch++) {
        int c0 = lft ? (224 - ch*32) : ch*32;
        #pragma unroll
        for (int r = 0; r < 32; r++)
            s[warp][r][lane] = src[(row0 + r)*Ww + c0 + lane];
        __syncwarp();
        if (!lft) {
            #pragma unroll
            for (int j = 0; j < 32; j++) {
                float v = s[warp][lane][j];
                h = fmaxf(fmaf(wc, h, v + bv), 0.f);
                s[warp][lane][j] = h;
            }
        } else {
            #pragma unroll
            for (int j = 31; j >= 0; j--) {
                float v = s[warp][lane][j];
                h = fmaxf(fmaf(wc, h, v + bv), 0.f);
                s[warp][lane][j] = h;
            }
        }
        __syncwarp();
        #pragma unroll
        for (int r = 0; r < 32; r++)
            dst[(row0 + r)*Ww + c0 + lane] = s[warp][r][lane];
        __syncwarp();
    }
}

// ================================================================================
// K3: out2 = relu( wD2[64x256] @ cat ). Block tile 64oc x 128px, 128 threads,
// thread = 16oc x 4px, looping over the 4 direction chunks.
// ================================================================================
__global__ __launch_bounds__(128)
void k_convD2(const float* __restrict__ wD2) {
    __shared__ __align__(16) float ws[64*64];
    __shared__ __align__(16) float xs[64*128];
    int tid = threadIdx.x;
    int blk = blockIdx.x;                 // 2048 blocks
    int b   = blk >> 9;
    int p0g = (blk & 511) * 128;
    int o0  = (tid >> 5) * 16;
    int p0  = (tid & 31) * 4;

    float2 acc[16][2];
    #pragma unroll
    for (int oo = 0; oo < 16; oo++) { acc[oo][0] = make_float2(0.f,0.f); acc[oo][1] = make_float2(0.f,0.f); }

    for (int d = 0; d < 4; d++) {
        __syncthreads();
        for (int t = tid; t < 4096; t += 128) {
            int o = t & 63, i = t >> 6;
            ws[t] = wD2[o*256 + d*64 + i];
        }
        const float* src = (const float*)g_dir[d] + (size_t)b*64*PP + p0g;
        for (int t = tid; t < 2048; t += 128) {
            int i = t >> 5, p4 = (t & 31) * 4;
            *(float4*)&xs[i*128 + p4] = *(const float4*)&src[(size_t)i*PP + p4];
        }
        __syncthreads();
        #pragma unroll 2
        for (int i = 0; i < 64; i++) {
            float4 w0 = *(const float4*)&ws[i*64 + o0];
            float4 w1 = *(const float4*)&ws[i*64 + o0 + 4];
            float4 w2_ = *(const float4*)&ws[i*64 + o0 + 8];
            float4 w3 = *(const float4*)&ws[i*64 + o0 + 12];
            float4 xv = *(const float4*)&xs[i*128 + p0];
            float2 x01 = make_float2(xv.x, xv.y);
            float2 x23 = make_float2(xv.z, xv.w);
            float wv[16] = {w0.x,w0.y,w0.z,w0.w, w1.x,w1.y,w1.z,w1.w,
                            w2_.x,w2_.y,w2_.z,w2_.w, w3.x,w3.y,w3.z,w3.w};
            #pragma unroll
            for (int oo = 0; oo < 16; oo++) {
                float2 w2 = make_float2(wv[oo], wv[oo]);
                acc[oo][0] = ffma2(w2, x01, acc[oo][0]);
                acc[oo][1] = ffma2(w2, x23, acc[oo][1]);
            }
        }
    }
    float* dst = g_t2 + (size_t)b*64*PP + p0g;
    #pragma unroll
    for (int oo = 0; oo < 16; oo++) {
        float4 v = make_float4(fmaxf(acc[oo][0].x, 0.f), fmaxf(acc[oo][0].y, 0.f),
                               fmaxf(acc[oo][1].x, 0.f), fmaxf(acc[oo][1].y, 0.f));
        *(float4*)&dst[(size_t)(o0+oo)*PP + p0] = v;
    }
}

// ================================================================================
// K4/K5: conv3x3 SAME + relu, OC=32, IC templated. CHU=8 ic-chunks.
// Block = 256 thr = 16x16 threads; each thread: 2 adjacent pixels x all 32 oc.
// ================================================================================
template<int IC, int LAYER>
__global__ __launch_bounds__(256)
void k_conv3(const float* __restrict__ wg, const float* __restrict__ bias) {
    constexpr int OC = 32;
    constexpr int CHU = 8;
    __shared__ __align__(16) float wsm[CHU*9*OC];     // 9KB
    __shared__ float in_s[CHU][18][36];               // 20.25KB

    const float* src = (LAYER == 0) ? g_t2 : g_a1;
    float*       dst = (LAYER == 0) ? g_a1 : g_a2;

    int tid = threadIdx.x;
    int tx = tid & 15, ty = tid >> 4;                  // 16x16 threads
    int blk = blockIdx.x;                              // 4 * 16 * 8 = 512
    int b   = blk >> 7;
    int t   = blk & 127;
    int ty0 = (t >> 3) * 16;
    int tx0 = (t & 7) * 32;
    const float* sb = src + (size_t)b*IC*PP;

    float2 acc0[16], acc1[16];
    #pragma unroll
    for (int op = 0; op < 16; op++) { acc0[op] = make_float2(0.f,0.f); acc1[op] = make_float2(0.f,0.f); }

    for (int ic0 = 0; ic0 < IC; ic0 += CHU) {
        __syncthreads();
        for (int tt = tid; tt < CHU*9*OC; tt += 256) {
            int oc = tt & 31;
            int rest = tt >> 5;
            int k = rest % 9, icl = rest / 9;
            wsm[tt] = wg[((oc*IC) + ic0 + icl)*9 + k];
        }
        for (int tt = tid; tt < CHU*18*34; tt += 256) {
            int col = tt % 34;
            int rr  = (tt / 34) % 18;
            int icl = tt / (34*18);
            int gy = ty0 + rr - 1, gx = tx0 + col - 1;
            float v = 0.f;
            if (gy >= 0 && gy < Hh && gx >= 0 && gx < Ww)
                v = sb[(size_t)(ic0 + icl)*PP + gy*Ww + gx];
            in_s[icl][rr][col] = v;
        }
        __syncthreads();

        for (int icl = 0; icl < CHU; icl++) {
            float xv[3][4];
            #pragma unroll
            for (int dy = 0; dy < 3; dy++)
                #pragma unroll
                for (int dx = 0; dx < 4; dx++)
                    xv[dy][dx] = in_s[icl][ty + dy][2*tx + dx];
            #pragma unroll
            for (int dy = 0; dy < 3; dy++) {
                #pragma unroll
                for (int dx = 0; dx < 3; dx++) {
                    int k = dy*3 + dx;
                    float2 x0 = make_float2(xv[dy][dx],   xv[dy][dx]);
                    float2 x1 = make_float2(xv[dy][dx+1], xv[dy][dx+1]);
                    const float4* w4 = (const float4*)&wsm[(icl*9 + k)*OC];
                    #pragma unroll
                    for (int q = 0; q < 8; q++) {
                        float4 wv = w4[q];
                        float2 wa = make_float2(wv.x, wv.y);
                        float2 wb = make_float2(wv.z, wv.w);
                        acc0[2*q]   = ffma2(wa, x0, acc0[2*q]);
                        acc0[2*q+1] = ffma2(wb, x0, acc0[2*q+1]);
                        acc1[2*q]   = ffma2(wa, x1, acc1[2*q]);
                        acc1[2*q+1] = ffma2(wb, x1, acc1[2*q+1]);
                    }
                }
            }
        }
    }
    int py = ty0 + ty, px = tx0 + 2*tx;
    #pragma unroll
    for (int op = 0; op < 16; op++) {
        float ba = bias[2*op], bbv = bias[2*op + 1];
        float2 vA = make_float2(fmaxf(acc0[op].x + ba, 0.f), fmaxf(acc1[op].x + ba, 0.f));
        float2 vB = make_float2(fmaxf(acc0[op].y + bbv, 0.f), fmaxf(acc1[op].y + bbv, 0.f));
        *(float2*)&dst[((size_t)b*OC + 2*op    )*PP + py*Ww + px] = vA;
        *(float2*)&dst[((size_t)b*OC + 2*op + 1)*PP + py*Ww + px] = vB;
    }
}

// ================================================================================
// K6: a = a3w @ g_a2 + a3b ; weight = sigmoid(a) ; out = relu(x * weight)
// ================================================================================
__global__ __launch_bounds__(256)
void k_final(const float* __restrict__ x, const float* __restrict__ a3w,
             const float* __restrict__ a3b, float* __restrict__ out) {
    int idx = blockIdx.x * 256 + threadIdx.x;       // 65536 float4 groups
    int b  = idx >> 14;
    int p4 = (idx & 16383) * 4;
    float4 acc = make_float4(0.f, 0.f, 0.f, 0.f);
    #pragma unroll 8
    for (int ic = 0; ic < 32; ic++) {
        float wv = a3w[ic];
        float4 v = *(const float4*)&g_a2[((size_t)b*32 + ic)*PP + p4];
        acc.x = fmaf(wv, v.x, acc.x);
        acc.y = fmaf(wv, v.y, acc.y);
        acc.z = fmaf(wv, v.z, acc.z);
        acc.w = fmaf(wv, v.w, acc.w);
    }
    float bb = a3b[0];
    float4 wt;
    wt.x = 1.f / (1.f + expf(-(acc.x + bb)));
    wt.y = 1.f / (1.f + expf(-(acc.y + bb)));
    wt.z = 1.f / (1.f + expf(-(acc.z + bb)));
    wt.w = 1.f / (1.f + expf(-(acc.w + bb)));
    #pragma unroll 4
    for (int c = 0; c < 64; c++) {
        float4 xv = *(const float4*)&x[((size_t)b*64 + c)*PP + p4];
        float4 o;
        o.x = fmaxf(xv.x * wt.x, 0.f);
        o.y = fmaxf(xv.y * wt.y, 0.f);
        o.z = fmaxf(xv.z * wt.z, 0.f);
        o.w = fmaxf(xv.w * wt.w, 0.f);
        *(float4*)&out[((size_t)b*64 + c)*PP + p4] = o;
    }
}

// ================================================================================
extern "C" void kernel_launch(void* const* d_in, const int* in_sizes, int n_in,
                              void* d_out, int out_size) {
    const float* x       = (const float*)d_in[0];
    const float* w_in    = (const float*)d_in[1];
    const float* w_up    = (const float*)d_in[2];
    const float* b_up    = (const float*)d_in[3];
    const float* w_right = (const float*)d_in[4];
    const float* b_right = (const float*)d_in[5];
    const float* w_down  = (const float*)d_in[6];
    const float* b_down  = (const float*)d_in[7];
    const float* w_left  = (const float*)d_in[8];
    const float* b_left  = (const float*)d_in[9];
    const float* wD2     = (const float*)d_in[10];
    const float* a1w     = (const float*)d_in[11];
    const float* a1b     = (const float*)d_in[12];
    const float* a2w     = (const float*)d_in[13];
    const float* a2b     = (const float*)d_in[14];
    const float* a3w     = (const float*)d_in[15];
    const float* a3b     = (const float*)d_in[16];
    float* out = (float*)d_out;

    k_conv_in<<<2048, 128>>>(x, w_in);
    dim3 gscan(Bb*Cc, 2);
    k_scan_v<<<gscan, 256>>>(w_up, b_up, w_down, b_down);
    k_scan_h<<<gscan, 256>>>(w_right, b_right, w_left, b_left);
    k_convD2<<<2048, 128>>>(wD2);
    k_conv3<64, 0><<<512, 256>>>(a1w, a1b);
    k_conv3<32, 1><<<512, 256>>>(a2w, a2b);
    k_final<<<256, 256>>>(x, a3w, a3b, out);
}

// round 7
// speedup vs baseline: 1.8439x; 1.1637x over previous
#include <cuda_runtime.h>
#include <math.h>

#define Bb 4
#define Cc 64
#define Hh 256
#define Ww 256
#define PP (Hh*Ww)          // 65536
#define CH 32

// ---------------- scratch (device globals; no runtime allocs allowed) ----------
__device__ float g_t0[Bb*Cc*PP];       // conv1x1-in output
__device__ float g_dir[4][Bb*Cc*PP];   // 0=up 1=right 2=down 3=left
__device__ float g_t2[Bb*Cc*PP];       // wD2 conv output
__device__ float g_a1[Bb*CH*PP];
__device__ float g_a2[Bb*CH*PP];
// transposed weights (filled once per launch by k_prep; cheap, deterministic)
__device__ float g_winT[64*64];        // [i*64+o]   = w_in[o,i]
__device__ float g_wT[4*64*64];        // [d][i*64+o]= wD2[o, d*64+i]
__device__ float g_w3T0[64*9*32];      // [(ic*9+k)*32+oc] = a1_w[oc,ic,k]
__device__ float g_w3T1[32*9*32];      // [(ic*9+k)*32+oc] = a2_w[oc,ic,k]

// ---------------- packed fp32x2 FMA (2x FFMA rate on sm_103a) ------------------
__device__ __forceinline__ float2 ffma2(float2 a, float2 b, float2 c) {
    unsigned long long ua = *reinterpret_cast<unsigned long long*>(&a);
    unsigned long long ub = *reinterpret_cast<unsigned long long*>(&b);
    unsigned long long uc = *reinterpret_cast<unsigned long long*>(&c);
    unsigned long long ud;
    asm("fma.rn.f32x2 %0, %1, %2, %3;" : "=l"(ud) : "l"(ua), "l"(ub), "l"(uc));
    return *reinterpret_cast<float2*>(&ud);
}

// ================================================================================
// K0: one-time weight transposes (runs every launch; ~48K elements, negligible)
// ================================================================================
__global__ __launch_bounds__(256)
void k_prep(const float* __restrict__ w_in, const float* __restrict__ wD2,
            const float* __restrict__ a1w, const float* __restrict__ a2w) {
    int idx = blockIdx.x * 256 + threadIdx.x;
    if (idx < 4096) {                                   // winT
        int i = idx >> 6, o = idx & 63;
        g_winT[idx] = w_in[o*64 + i];
        return;
    }
    idx -= 4096;
    if (idx < 4*4096) {                                 // wT
        int d = idx >> 12, r = idx & 4095;
        int i = r >> 6, o = r & 63;
        g_wT[idx] = wD2[o*256 + d*64 + i];
        return;
    }
    idx -= 4*4096;
    if (idx < 64*9*32) {                                // w3T0
        int oc = idx & 31, k = (idx >> 5) % 9, ic = idx / (9*32);
        g_w3T0[idx] = a1w[(oc*64 + ic)*9 + k];
        return;
    }
    idx -= 64*9*32;
    if (idx < 32*9*32) {                                // w3T1
        int oc = idx & 31, k = (idx >> 5) % 9, ic = idx / (9*32);
        g_w3T1[idx] = a2w[(oc*32 + ic)*9 + k];
    }
}

// ================================================================================
// K1: out = w_in[64x64] @ x. Block tile 64oc x 128px, 128 threads,
// thread = 16oc x 4px. Weight staging now coalesced float4 from g_winT.
// ================================================================================
__global__ __launch_bounds__(128)
void k_conv_in(const float* __restrict__ x) {
    __shared__ __align__(16) float ws[64*64];    // ws[i*64+o]  16KB
    __shared__ __align__(16) float xs[64*128];   // xs[i*128+p] 32KB
    int tid = threadIdx.x;
    int blk = blockIdx.x;                 // 2048 blocks
    int b   = blk >> 9;
    int p0g = (blk & 511) * 128;
    int o0  = (tid >> 5) * 16;            // warp-uniform, 4 warps
    int p0  = (tid & 31) * 4;

    for (int t = tid; t < 1024; t += 128)
        ((float4*)ws)[t] = ((const float4*)g_winT)[t];
    const float* src = x + (size_t)b*64*PP + p0g;
    for (int t = tid; t < 2048; t += 128) {
        int i = t >> 5, p4 = (t & 31) * 4;
        *(float4*)&xs[i*128 + p4] = *(const float4*)&src[(size_t)i*PP + p4];
    }
    __syncthreads();

    float2 acc[16][2];
    #pragma unroll
    for (int oo = 0; oo < 16; oo++) { acc[oo][0] = make_float2(0.f,0.f); acc[oo][1] = make_float2(0.f,0.f); }

    #pragma unroll 2
    for (int i = 0; i < 64; i++) {
        float4 w0 = *(const float4*)&ws[i*64 + o0];
        float4 w1 = *(const float4*)&ws[i*64 + o0 + 4];
        float4 w2_ = *(const float4*)&ws[i*64 + o0 + 8];
        float4 w3 = *(const float4*)&ws[i*64 + o0 + 12];
        float4 xv = *(const float4*)&xs[i*128 + p0];
        float2 x01 = make_float2(xv.x, xv.y);
        float2 x23 = make_float2(xv.z, xv.w);
        float wv[16] = {w0.x,w0.y,w0.z,w0.w, w1.x,w1.y,w1.z,w1.w,
                        w2_.x,w2_.y,w2_.z,w2_.w, w3.x,w3.y,w3.z,w3.w};
        #pragma unroll
        for (int oo = 0; oo < 16; oo++) {
            float2 w2 = make_float2(wv[oo], wv[oo]);
            acc[oo][0] = ffma2(w2, x01, acc[oo][0]);
            acc[oo][1] = ffma2(w2, x23, acc[oo][1]);
        }
    }
    float* dst = g_t0 + (size_t)b*64*PP + p0g;
    #pragma unroll
    for (int oo = 0; oo < 16; oo++) {
        float4 v = make_float4(acc[oo][0].x, acc[oo][0].y, acc[oo][1].x, acc[oo][1].y);
        *(float4*)&dst[(size_t)(o0+oo)*PP + p0] = v;
    }
}

// ================================================================================
// K2v: vertical IRNN scans. blockIdx.x = b*64+c, blockIdx.y: 0=down(fwd) 1=up(rev)
// ================================================================================
__global__ __launch_bounds__(256)
void k_scan_v(const float* __restrict__ w_up, const float* __restrict__ b_up,
              const float* __restrict__ w_down, const float* __restrict__ b_down) {
    int bc = blockIdx.x;
    int c  = bc & 63;
    int up = blockIdx.y;
    int w  = threadIdx.x;
    const float* src = g_t0 + (size_t)bc*PP;
    float* dst = (up ? g_dir[0] : g_dir[2]) + (size_t)bc*PP;
    float wc = up ? w_up[c] : w_down[c];
    float bv = up ? b_up[c] : b_down[c];
    float h = 0.f;
    if (!up) {
        float v = src[w];
        #pragma unroll 4
        for (int y = 0; y < Hh; y++) {
            float vn = (y < Hh-1) ? src[(y+1)*Ww + w] : 0.f;
            h = fmaxf(fmaf(wc, h, v + bv), 0.f);
            dst[y*Ww + w] = h;
            v = vn;
        }
    } else {
        float v = src[(Hh-1)*Ww + w];
        #pragma unroll 4
        for (int y = Hh-1; y >= 0; y--) {
            float vn = (y > 0) ? src[(y-1)*Ww + w] : 0.f;
            h = fmaxf(fmaf(wc, h, v + bv), 0.f);
            dst[y*Ww + w] = h;
            v = vn;
        }
    }
}

// ================================================================================
// K2h: horizontal IRNN scans via warp-owned 32x32 smem transpose tiles.
// ================================================================================
__global__ __launch_bounds__(256)
void k_scan_h(const float* __restrict__ w_right, const float* __restrict__ b_right,
              const float* __restrict__ w_left, const float* __restrict__ b_left) {
    __shared__ float s[8][32][33];
    int bc = blockIdx.x;
    int c  = bc & 63;
    int lft = blockIdx.y;
    int lane = threadIdx.x & 31, warp = threadIdx.x >> 5;
    const float* src = g_t0 + (size_t)bc*PP;
    float* dst = (lft ? g_dir[3] : g_dir[1]) + (size_t)bc*PP;
    float wc = lft ? w_left[c] : w_right[c];
    float bv = lft ? b_left[c] : b_right[c];
    int row0 = warp * 32;
    float h = 0.f;
    for (int ch = 0; ch < 8; ch++) {
        int c0 = lft ? (224 - ch*32) : ch*32;
        #pragma unroll
        for (int r = 0; r < 32; r++)
            s[warp][r][lane] = src[(row0 + r)*Ww + c0 + lane];
        __syncwarp();
        if (!lft) {
            #pragma unroll
            for (int j = 0; j < 32; j++) {
                float v = s[warp][lane][j];
                h = fmaxf(fmaf(wc, h, v + bv), 0.f);
                s[warp][lane][j] = h;
            }
        } else {
            #pragma unroll
            for (int j = 31; j >= 0; j--) {
                float v = s[warp][lane][j];
                h = fmaxf(fmaf(wc, h, v + bv), 0.f);
                s[warp][lane][j] = h;
            }
        }
        __syncwarp();
        #pragma unroll
        for (int r = 0; r < 32; r++)
            dst[(row0 + r)*Ww + c0 + lane] = s[warp][r][lane];
        __syncwarp();
    }
}

// ================================================================================
// K3: out2 = relu( wD2[64x256] @ cat ). Block tile 64oc x 128px, 128 threads,
// thread = 16oc x 4px, 4 direction chunks. Coalesced weight staging from g_wT.
// ================================================================================
__global__ __launch_bounds__(128)
void k_convD2() {
    __shared__ __align__(16) float ws[64*64];
    __shared__ __align__(16) float xs[64*128];
    int tid = threadIdx.x;
    int blk = blockIdx.x;                 // 2048 blocks
    int b   = blk >> 9;
    int p0g = (blk & 511) * 128;
    int o0  = (tid >> 5) * 16;
    int p0  = (tid & 31) * 4;

    float2 acc[16][2];
    #pragma unroll
    for (int oo = 0; oo < 16; oo++) { acc[oo][0] = make_float2(0.f,0.f); acc[oo][1] = make_float2(0.f,0.f); }

    for (int d = 0; d < 4; d++) {
        __syncthreads();
        const float4* wsrc = (const float4*)(g_wT + d*4096);
        for (int t = tid; t < 1024; t += 128)
            ((float4*)ws)[t] = wsrc[t];
        const float* src = (const float*)g_dir[d] + (size_t)b*64*PP + p0g;
        for (int t = tid; t < 2048; t += 128) {
            int i = t >> 5, p4 = (t & 31) * 4;
            *(float4*)&xs[i*128 + p4] = *(const float4*)&src[(size_t)i*PP + p4];
        }
        __syncthreads();
        #pragma unroll 2
        for (int i = 0; i < 64; i++) {
            float4 w0 = *(const float4*)&ws[i*64 + o0];
            float4 w1 = *(const float4*)&ws[i*64 + o0 + 4];
            float4 w2_ = *(const float4*)&ws[i*64 + o0 + 8];
            float4 w3 = *(const float4*)&ws[i*64 + o0 + 12];
            float4 xv = *(const float4*)&xs[i*128 + p0];
            float2 x01 = make_float2(xv.x, xv.y);
            float2 x23 = make_float2(xv.z, xv.w);
            float wv[16] = {w0.x,w0.y,w0.z,w0.w, w1.x,w1.y,w1.z,w1.w,
                            w2_.x,w2_.y,w2_.z,w2_.w, w3.x,w3.y,w3.z,w3.w};
            #pragma unroll
            for (int oo = 0; oo < 16; oo++) {
                float2 w2 = make_float2(wv[oo], wv[oo]);
                acc[oo][0] = ffma2(w2, x01, acc[oo][0]);
                acc[oo][1] = ffma2(w2, x23, acc[oo][1]);
            }
        }
    }
    float* dst = g_t2 + (size_t)b*64*PP + p0g;
    #pragma unroll
    for (int oo = 0; oo < 16; oo++) {
        float4 v = make_float4(fmaxf(acc[oo][0].x, 0.f), fmaxf(acc[oo][0].y, 0.f),
                               fmaxf(acc[oo][1].x, 0.f), fmaxf(acc[oo][1].y, 0.f));
        *(float4*)&dst[(size_t)(o0+oo)*PP + p0] = v;
    }
}

// ================================================================================
// K4/K5: conv3x3 SAME + relu, OC=32, IC templated. CHU=8 ic-chunks.
// Block = 256 thr = 16x16 threads; thread: 2 adjacent px x all 32 oc.
// Weight staging now coalesced float4 from transposed g_w3T*.
// ================================================================================
template<int IC, int LAYER>
__global__ __launch_bounds__(256)
void k_conv3(const float* __restrict__ bias) {
    constexpr int OC = 32;
    constexpr int CHU = 8;
    __shared__ __align__(16) float wsm[CHU*9*OC];     // 9KB
    __shared__ float in_s[CHU][18][36];               // 20.25KB

    const float* src = (LAYER == 0) ? g_t2 : g_a1;
    float*       dst = (LAYER == 0) ? g_a1 : g_a2;
    const float* wT  = (LAYER == 0) ? g_w3T0 : g_w3T1;

    int tid = threadIdx.x;
    int tx = tid & 15, ty = tid >> 4;                  // 16x16 threads
    int blk = blockIdx.x;                              // 4 * 16 * 8 = 512
    int b   = blk >> 7;
    int t   = blk & 127;
    int ty0 = (t >> 3) * 16;
    int tx0 = (t & 7) * 32;
    const float* sb = src + (size_t)b*IC*PP;

    float2 acc0[16], acc1[16];
    #pragma unroll
    for (int op = 0; op < 16; op++) { acc0[op] = make_float2(0.f,0.f); acc1[op] = make_float2(0.f,0.f); }

    for (int ic0 = 0; ic0 < IC; ic0 += CHU) {
        __syncthreads();
        const float4* wsrc = (const float4*)(wT + ic0*9*OC);
        for (int tt = tid; tt < CHU*9*OC/4; tt += 256)
            ((float4*)wsm)[tt] = wsrc[tt];
        for (int tt = tid; tt < CHU*18*34; tt += 256) {
            int col = tt % 34;
            int rr  = (tt / 34) % 18;
            int icl = tt / (34*18);
            int gy = ty0 + rr - 1, gx = tx0 + col - 1;
            float v = 0.f;
            if (gy >= 0 && gy < Hh && gx >= 0 && gx < Ww)
                v = sb[(size_t)(ic0 + icl)*PP + gy*Ww + gx];
            in_s[icl][rr][col] = v;
        }
        __syncthreads();

        for (int icl = 0; icl < CHU; icl++) {
            float xv[3][4];
            #pragma unroll
            for (int dy = 0; dy < 3; dy++)
                #pragma unroll
                for (int dx = 0; dx < 4; dx++)
                    xv[dy][dx] = in_s[icl][ty + dy][2*tx + dx];
            #pragma unroll
            for (int dy = 0; dy < 3; dy++) {
                #pragma unroll
                for (int dx = 0; dx < 3; dx++) {
                    int k = dy*3 + dx;
                    float2 x0 = make_float2(xv[dy][dx],   xv[dy][dx]);
                    float2 x1 = make_float2(xv[dy][dx+1], xv[dy][dx+1]);
                    const float4* w4 = (const float4*)&wsm[(icl*9 + k)*OC];
                    #pragma unroll
                    for (int q = 0; q < 8; q++) {
                        float4 wv = w4[q];
                        float2 wa = make_float2(wv.x, wv.y);
                        float2 wb = make_float2(wv.z, wv.w);
                        acc0[2*q]   = ffma2(wa, x0, acc0[2*q]);
                        acc0[2*q+1] = ffma2(wb, x0, acc0[2*q+1]);
                        acc1[2*q]   = ffma2(wa, x1, acc1[2*q]);
                        acc1[2*q+1] = ffma2(wb, x1, acc1[2*q+1]);
                    }
                }
            }
        }
    }
    int py = ty0 + ty, px = tx0 + 2*tx;
    #pragma unroll
    for (int op = 0; op < 16; op++) {
        float ba = bias[2*op], bbv = bias[2*op + 1];
        float2 vA = make_float2(fmaxf(acc0[op].x + ba, 0.f), fmaxf(acc1[op].x + ba, 0.f));
        float2 vB = make_float2(fmaxf(acc0[op].y + bbv, 0.f), fmaxf(acc1[op].y + bbv, 0.f));
        *(float2*)&dst[((size_t)b*OC + 2*op    )*PP + py*Ww + px] = vA;
        *(float2*)&dst[((size_t)b*OC + 2*op + 1)*PP + py*Ww + px] = vB;
    }
}

// ================================================================================
// K6: a = a3w @ g_a2 + a3b ; weight = sigmoid(a) ; out = relu(x * weight)
// ================================================================================
__global__ __launch_bounds__(256)
void k_final(const float* __restrict__ x, const float* __restrict__ a3w,
             const float* __restrict__ a3b, float* __restrict__ out) {
    int idx = blockIdx.x * 256 + threadIdx.x;       // 65536 float4 groups
    int b  = idx >> 14;
    int p4 = (idx & 16383) * 4;
    float4 acc = make_float4(0.f, 0.f, 0.f, 0.f);
    #pragma unroll 8
    for (int ic = 0; ic < 32; ic++) {
        float wv = a3w[ic];
        float4 v = *(const float4*)&g_a2[((size_t)b*32 + ic)*PP + p4];
        acc.x = fmaf(wv, v.x, acc.x);
        acc.y = fmaf(wv, v.y, acc.y);
        acc.z = fmaf(wv, v.z, acc.z);
        acc.w = fmaf(wv, v.w, acc.w);
    }
    float bb = a3b[0];
    float4 wt;
    wt.x = 1.f / (1.f + expf(-(acc.x + bb)));
    wt.y = 1.f / (1.f + expf(-(acc.y + bb)));
    wt.z = 1.f / (1.f + expf(-(acc.z + bb)));
    wt.w = 1.f / (1.f + expf(-(acc.w + bb)));
    #pragma unroll 4
    for (int c = 0; c < 64; c++) {
        float4 xv = *(const float4*)&x[((size_t)b*64 + c)*PP + p4];
        float4 o;
        o.x = fmaxf(xv.x * wt.x, 0.f);
        o.y = fmaxf(xv.y * wt.y, 0.f);
        o.z = fmaxf(xv.z * wt.z, 0.f);
        o.w = fmaxf(xv.w * wt.w, 0.f);
        *(float4*)&out[((size_t)b*64 + c)*PP + p4] = o;
    }
}

// ================================================================================
extern "C" void kernel_launch(void* const* d_in, const int* in_sizes, int n_in,
                              void* d_out, int out_size) {
    const float* x       = (const float*)d_in[0];
    const float* w_in    = (const float*)d_in[1];
    const float* w_up    = (const float*)d_in[2];
    const float* b_up    = (const float*)d_in[3];
    const float* w_right = (const float*)d_in[4];
    const float* b_right = (const float*)d_in[5];
    const float* w_down  = (const float*)d_in[6];
    const float* b_down  = (const float*)d_in[7];
    const float* w_left  = (const float*)d_in[8];
    const float* b_left  = (const float*)d_in[9];
    const float* wD2     = (const float*)d_in[10];
    const float* a1w     = (const float*)d_in[11];
    const float* a1b     = (const float*)d_in[12];
    const float* a2w     = (const float*)d_in[13];
    const float* a2b     = (const float*)d_in[14];
    const float* a3w     = (const float*)d_in[15];
    const float* a3b     = (const float*)d_in[16];
    float* out = (float*)d_out;

    k_prep<<<189, 256>>>(w_in, wD2, a1w, a2w);
    k_conv_in<<<2048, 128>>>(x);
    dim3 gscan(Bb*Cc, 2);
    k_scan_v<<<gscan, 256>>>(w_up, b_up, w_down, b_down);
    k_scan_h<<<gscan, 256>>>(w_right, b_right, w_left, b_left);
    k_convD2<<<2048, 128>>>();
    k_conv3<64, 0><<<512, 256>>>(a1b);
    k_conv3<32, 1><<<512, 256>>>(a2b);
    k_final<<<256, 256>>>(x, a3w, a3b, out);
}

// round 8
// speedup vs baseline: 2.7615x; 1.4976x over previous
#include <cuda_runtime.h>
#include <math.h>

#define Bb 4
#define Cc 64
#define Hh 256
#define Ww 256
#define PP (Hh*Ww)          // 65536
#define CH 32

// ---------------- scratch (device globals; no runtime allocs allowed) ----------
__device__ float g_t0[Bb*Cc*PP];       // conv1x1-in output
__device__ float g_dir[4][Bb*Cc*PP];   // 0=up 1=right 2=down 3=left (tf32-rounded)
__device__ float g_t2[Bb*Cc*PP];       // wD2 conv output
__device__ float g_a1[Bb*CH*PP];
__device__ float g_a2[Bb*CH*PP];
// transposed + tf32-rounded weights (filled by k_prep each launch)
__device__ float g_winT[64*64];        // [k*64+o]   = w_in[o,k]
__device__ float g_wT[4*64*64];        // [d][k*64+o]= wD2[o, d*64+k]
__device__ float g_w3T0[64*9*32];      // [(ic*9+tap)*32+oc] = a1_w[oc,ic,tap]
__device__ float g_w3T1[32*9*32];      // [(ic*9+tap)*32+oc] = a2_w[oc,ic,tap]

// ---------------- helpers ------------------------------------------------------
__device__ __forceinline__ float tf32r(float f) {
    unsigned u;
    asm("cvt.rna.tf32.f32 %0, %1;" : "=r"(u) : "f"(f));
    return __uint_as_float(u);
}

// m16n8k8 tf32 mma: D += A*B  (fragments per PTX ISA)
__device__ __forceinline__ void mma_tf32(float* c, const unsigned* a, const unsigned* b) {
    asm volatile("mma.sync.aligned.m16n8k8.row.col.f32.tf32.tf32.f32 "
        "{%0,%1,%2,%3}, {%4,%5,%6,%7}, {%8,%9}, {%0,%1,%2,%3};"
        : "+f"(c[0]), "+f"(c[1]), "+f"(c[2]), "+f"(c[3])
        : "r"(a[0]), "r"(a[1]), "r"(a[2]), "r"(a[3]), "r"(b[0]), "r"(b[1]));
}

// ================================================================================
// K0: weight transposes + tf32 rounding. 48128 elements total, grid 188x256.
// ================================================================================
__global__ __launch_bounds__(256)
void k_prep(const float* __restrict__ w_in, const float* __restrict__ wD2,
            const float* __restrict__ a1w, const float* __restrict__ a2w) {
    int idx = blockIdx.x * 256 + threadIdx.x;
    if (idx < 4096) {                                   // winT
        int k = idx >> 6, o = idx & 63;
        g_winT[idx] = tf32r(w_in[o*64 + k]);
        return;
    }
    idx -= 4096;
    if (idx < 4*4096) {                                 // wT
        int d = idx >> 12, r = idx & 4095;
        int k = r >> 6, o = r & 63;
        g_wT[idx] = tf32r(wD2[o*256 + d*64 + k]);
        return;
    }
    idx -= 4*4096;
    if (idx < 64*9*32) {                                // w3T0
        int oc = idx & 31, tap = (idx >> 5) % 9, ic = idx / (9*32);
        g_w3T0[idx] = tf32r(a1w[(oc*64 + ic)*9 + tap]);
        return;
    }
    idx -= 64*9*32;
    if (idx < 32*9*32) {                                // w3T1
        int oc = idx & 31, tap = (idx >> 5) % 9, ic = idx / (9*32);
        g_w3T1[idx] = tf32r(a2w[(oc*32 + ic)*9 + tap]);
    }
}

// ================================================================================
// K1: g_t0 = w_in @ x via tf32 mma. Block 128 thr/4 warps, tile 64oc x 128px.
// Warp w: oc0=16w, 16 n-tiles of 8px, K=64. XOR-8 swizzled smem (conflict-free).
// ================================================================================
__global__ __launch_bounds__(128)
void k_conv_in(const float* __restrict__ x) {
    __shared__ __align__(16) float ws[64*64];    // phys col = oc ^ (8*(k&3))
    __shared__ __align__(16) float xs[64*128];   // phys col = px ^ (8*(k&3))
    int tid  = threadIdx.x;
    int lane = tid & 31, warp = tid >> 5;
    int lr = lane >> 2, lc = lane & 3;
    int blk = blockIdx.x;                 // 2048
    int b   = blk >> 9;
    int p0g = (blk & 511) * 128;
    int oc0 = warp * 16;

    for (int t = tid; t < 4096; t += 128) {
        int k = t >> 6, oc = t & 63;
        ws[k*64 + (oc ^ (8*(k&3)))] = g_winT[t];
    }
    const float* src = x + (size_t)b*64*PP + p0g;
    for (int t = tid; t < 2048; t += 128) {
        int k = t >> 5, p4 = (t & 31) * 4;
        float4 v = *(const float4*)&src[(size_t)k*PP + p4];
        v.x = tf32r(v.x); v.y = tf32r(v.y); v.z = tf32r(v.z); v.w = tf32r(v.w);
        *(float4*)&xs[k*128 + (p4 ^ (8*(k&3)))] = v;
    }
    __syncthreads();

    float acc[16][4];
    #pragma unroll
    for (int j = 0; j < 16; j++) { acc[j][0]=0.f; acc[j][1]=0.f; acc[j][2]=0.f; acc[j][3]=0.f; }

    #pragma unroll
    for (int kk = 0; kk < 8; kk++) {
        unsigned a[4];
        int sw = 8*lc;
        a[0] = __float_as_uint(ws[(8*kk+lc)*64   + ((oc0+lr)   ^ sw)]);
        a[1] = __float_as_uint(ws[(8*kk+lc)*64   + ((oc0+lr+8) ^ sw)]);
        a[2] = __float_as_uint(ws[(8*kk+4+lc)*64 + ((oc0+lr)   ^ sw)]);
        a[3] = __float_as_uint(ws[(8*kk+4+lc)*64 + ((oc0+lr+8) ^ sw)]);
        #pragma unroll
        for (int j = 0; j < 16; j++) {
            unsigned bfr[2];
            bfr[0] = __float_as_uint(xs[(8*kk+lc)*128   + ((8*j+lr) ^ sw)]);
            bfr[1] = __float_as_uint(xs[(8*kk+4+lc)*128 + ((8*j+lr) ^ sw)]);
            mma_tf32(acc[j], a, bfr);
        }
    }
    float* dst = g_t0 + (size_t)b*64*PP + p0g;
    #pragma unroll
    for (int j = 0; j < 16; j++) {
        int px = 8*j + 2*lc;
        *(float2*)&dst[(size_t)(oc0+lr)*PP + px]   = make_float2(acc[j][0], acc[j][1]);
        *(float2*)&dst[(size_t)(oc0+lr+8)*PP + px] = make_float2(acc[j][2], acc[j][3]);
    }
}

// ================================================================================
// K2v: vertical IRNN scans (fp32 recurrence, tf32-rounded stores for convD2).
// ================================================================================
__global__ __launch_bounds__(256)
void k_scan_v(const float* __restrict__ w_up, const float* __restrict__ b_up,
              const float* __restrict__ w_down, const float* __restrict__ b_down) {
    int bc = blockIdx.x;
    int c  = bc & 63;
    int up = blockIdx.y;
    int w  = threadIdx.x;
    const float* src = g_t0 + (size_t)bc*PP;
    float* dst = (up ? g_dir[0] : g_dir[2]) + (size_t)bc*PP;
    float wc = up ? w_up[c] : w_down[c];
    float bv = up ? b_up[c] : b_down[c];
    float h = 0.f;
    if (!up) {
        float v = src[w];
        #pragma unroll 4
        for (int y = 0; y < Hh; y++) {
            float vn = (y < Hh-1) ? src[(y+1)*Ww + w] : 0.f;
            h = fmaxf(fmaf(wc, h, v + bv), 0.f);
            dst[y*Ww + w] = tf32r(h);
            v = vn;
        }
    } else {
        float v = src[(Hh-1)*Ww + w];
        #pragma unroll 4
        for (int y = Hh-1; y >= 0; y--) {
            float vn = (y > 0) ? src[(y-1)*Ww + w] : 0.f;
            h = fmaxf(fmaf(wc, h, v + bv), 0.f);
            dst[y*Ww + w] = tf32r(h);
            v = vn;
        }
    }
}

// ================================================================================
// K2h: horizontal IRNN scans via warp-owned 32x32 smem transpose tiles.
// ================================================================================
__global__ __launch_bounds__(256)
void k_scan_h(const float* __restrict__ w_right, const float* __restrict__ b_right,
              const float* __restrict__ w_left, const float* __restrict__ b_left) {
    __shared__ float s[8][32][33];
    int bc = blockIdx.x;
    int c  = bc & 63;
    int lft = blockIdx.y;
    int lane = threadIdx.x & 31, warp = threadIdx.x >> 5;
    const float* src = g_t0 + (size_t)bc*PP;
    float* dst = (lft ? g_dir[3] : g_dir[1]) + (size_t)bc*PP;
    float wc = lft ? w_left[c] : w_right[c];
    float bv = lft ? b_left[c] : b_right[c];
    int row0 = warp * 32;
    float h = 0.f;
    for (int ch = 0; ch < 8; ch++) {
        int c0 = lft ? (224 - ch*32) : ch*32;
        #pragma unroll
        for (int r = 0; r < 32; r++)
            s[warp][r][lane] = src[(row0 + r)*Ww + c0 + lane];
        __syncwarp();
        if (!lft) {
            #pragma unroll
            for (int j = 0; j < 32; j++) {
                float v = s[warp][lane][j];
                h = fmaxf(fmaf(wc, h, v + bv), 0.f);
                s[warp][lane][j] = tf32r(h);
            }
        } else {
            #pragma unroll
            for (int j = 31; j >= 0; j--) {
                float v = s[warp][lane][j];
                h = fmaxf(fmaf(wc, h, v + bv), 0.f);
                s[warp][lane][j] = tf32r(h);
            }
        }
        __syncwarp();
        #pragma unroll
        for (int r = 0; r < 32; r++)
            dst[(row0 + r)*Ww + c0 + lane] = s[warp][r][lane];
        __syncwarp();
    }
}

// ================================================================================
// K3: g_t2 = relu(wD2 @ cat) via tf32 mma. Same tiling as K1, 4 direction chunks
// (g_dir already tf32-rounded by scans; g_wT pre-rounded).
// ================================================================================
__global__ __launch_bounds__(128)
void k_convD2() {
    __shared__ __align__(16) float ws[64*64];
    __shared__ __align__(16) float xs[64*128];
    int tid  = threadIdx.x;
    int lane = tid & 31, warp = tid >> 5;
    int lr = lane >> 2, lc = lane & 3;
    int blk = blockIdx.x;                 // 2048
    int b   = blk >> 9;
    int p0g = (blk & 511) * 128;
    int oc0 = warp * 16;

    float acc[16][4];
    #pragma unroll
    for (int j = 0; j < 16; j++) { acc[j][0]=0.f; acc[j][1]=0.f; acc[j][2]=0.f; acc[j][3]=0.f; }

    for (int d = 0; d < 4; d++) {
        __syncthreads();
        const float* wsrc = g_wT + d*4096;
        for (int t = tid; t < 4096; t += 128) {
            int k = t >> 6, oc = t & 63;
            ws[k*64 + (oc ^ (8*(k&3)))] = wsrc[t];
        }
        const float* src = (const float*)g_dir[d] + (size_t)b*64*PP + p0g;
        for (int t = tid; t < 2048; t += 128) {
            int k = t >> 5, p4 = (t & 31) * 4;
            float4 v = *(const float4*)&src[(size_t)k*PP + p4];
            *(float4*)&xs[k*128 + (p4 ^ (8*(k&3)))] = v;
        }
        __syncthreads();
        #pragma unroll
        for (int kk = 0; kk < 8; kk++) {
            unsigned a[4];
            int sw = 8*lc;
            a[0] = __float_as_uint(ws[(8*kk+lc)*64   + ((oc0+lr)   ^ sw)]);
            a[1] = __float_as_uint(ws[(8*kk+lc)*64   + ((oc0+lr+8) ^ sw)]);
            a[2] = __float_as_uint(ws[(8*kk+4+lc)*64 + ((oc0+lr)   ^ sw)]);
            a[3] = __float_as_uint(ws[(8*kk+4+lc)*64 + ((oc0+lr+8) ^ sw)]);
            #pragma unroll
            for (int j = 0; j < 16; j++) {
                unsigned bfr[2];
                bfr[0] = __float_as_uint(xs[(8*kk+lc)*128   + ((8*j+lr) ^ sw)]);
                bfr[1] = __float_as_uint(xs[(8*kk+4+lc)*128 + ((8*j+lr) ^ sw)]);
                mma_tf32(acc[j], a, bfr);
            }
        }
    }
    float* dst = g_t2 + (size_t)b*64*PP + p0g;
    #pragma unroll
    for (int j = 0; j < 16; j++) {
        int px = 8*j + 2*lc;
        *(float2*)&dst[(size_t)(oc0+lr)*PP + px] =
            make_float2(fmaxf(acc[j][0],0.f), fmaxf(acc[j][1],0.f));
        *(float2*)&dst[(size_t)(oc0+lr+8)*PP + px] =
            make_float2(fmaxf(acc[j][2],0.f), fmaxf(acc[j][3],0.f));
    }
}

// ================================================================================
// K4/K5: conv3x3 SAME + relu via tf32 mma (implicit GEMM over taps).
// Block 128 thr/4 warps. Out tile: 32oc x (32x by 8y = 256px). Warp w: 2 y-rows,
// 8 n-tiles, 2 m-tiles. K per stage = 8 ic x 9 taps (kstep = tap, K8 = ic).
// ================================================================================
template<int IC, int LAYER>
__global__ __launch_bounds__(128)
void k_conv3(const float* __restrict__ bias) {
    constexpr int OC = 32;
    constexpr int CHU = 8;
    __shared__ __align__(16) float wsm[9*CHU*32];     // [(tap*8+icl)*32 + oc^(8*(icl&3))]
    __shared__ float in_s[CHU][10][36];               // ic-stride 360 == 8 mod 32

    const float* src = (LAYER == 0) ? g_t2 : g_a1;
    float*       dst = (LAYER == 0) ? g_a1 : g_a2;
    const float* wT  = (LAYER == 0) ? g_w3T0 : g_w3T1;

    int tid  = threadIdx.x;
    int lane = tid & 31, warp = tid >> 5;
    int lr = lane >> 2, lc = lane & 3;
    int blk = blockIdx.x;                              // 4 * 32 * 8 = 1024
    int b   = blk >> 8;
    int t   = blk & 255;
    int ty0 = (t >> 3) * 8;                            // 32 y-tiles of 8
    int tx0 = (t & 7) * 32;                            // 8 x-tiles of 32
    const float* sb = src + (size_t)b*IC*PP;

    float acc[2][8][4];
    #pragma unroll
    for (int m = 0; m < 2; m++)
        #pragma unroll
        for (int j = 0; j < 8; j++)
            { acc[m][j][0]=0.f; acc[m][j][1]=0.f; acc[m][j][2]=0.f; acc[m][j][3]=0.f; }

    for (int ic0 = 0; ic0 < IC; ic0 += CHU) {
        __syncthreads();
        const float* wsrc = wT + ic0*9*32;
        for (int tt = tid; tt < 9*CHU*32; tt += 128) {
            int oc = tt & 31;
            int q  = tt >> 5;                          // icl*9 + tap  (source order)
            int tap = q % 9, icl = q / 9;
            wsm[(tap*8 + icl)*32 + (oc ^ (8*(icl&3)))] = wsrc[tt];
        }
        for (int tt = tid; tt < CHU*10*34; tt += 128) {
            int col = tt % 34;
            int rr  = (tt / 34) % 10;
            int icl = tt / 340;
            int gy = ty0 + rr - 1, gx = tx0 + col - 1;
            float v = 0.f;
            if (gy >= 0 && gy < Hh && gx >= 0 && gx < Ww)
                v = tf32r(sb[(size_t)(ic0 + icl)*PP + gy*Ww + gx]);
            in_s[icl][rr][col] = v;
        }
        __syncthreads();

        #pragma unroll
        for (int tap = 0; tap < 9; tap++) {
            int dy = tap / 3, dx = tap % 3;
            unsigned aA[4], aB[4];
            int sw = 8*lc;
            aA[0] = __float_as_uint(wsm[(tap*8+lc)*32   + ((lr)    ^ sw)]);
            aA[1] = __float_as_uint(wsm[(tap*8+lc)*32   + ((lr+8)  ^ sw)]);
            aA[2] = __float_as_uint(wsm[(tap*8+lc+4)*32 + ((lr)    ^ sw)]);
            aA[3] = __float_as_uint(wsm[(tap*8+lc+4)*32 + ((lr+8)  ^ sw)]);
            aB[0] = __float_as_uint(wsm[(tap*8+lc)*32   + ((lr+16) ^ sw)]);
            aB[1] = __float_as_uint(wsm[(tap*8+lc)*32   + ((lr+24) ^ sw)]);
            aB[2] = __float_as_uint(wsm[(tap*8+lc+4)*32 + ((lr+16) ^ sw)]);
            aB[3] = __float_as_uint(wsm[(tap*8+lc+4)*32 + ((lr+24) ^ sw)]);
            #pragma unroll
            for (int j = 0; j < 8; j++) {
                int y = 2*warp + (j >> 2);
                int x = 8*(j & 3) + lr;
                unsigned bfr[2];
                bfr[0] = __float_as_uint(in_s[lc]  [y+dy][x+dx]);
                bfr[1] = __float_as_uint(in_s[lc+4][y+dy][x+dx]);
                mma_tf32(acc[0][j], aA, bfr);
                mma_tf32(acc[1][j], aB, bfr);
            }
        }
    }
    #pragma unroll
    for (int m = 0; m < 2; m++) {
        int ocA = 16*m + lr, ocB = 16*m + lr + 8;
        float bA = bias[ocA], bB = bias[ocB];
        #pragma unroll
        for (int j = 0; j < 8; j++) {
            int py = ty0 + 2*warp + (j >> 2);
            int px = tx0 + 8*(j & 3) + 2*lc;
            *(float2*)&dst[((size_t)b*OC + ocA)*PP + py*Ww + px] =
                make_float2(fmaxf(acc[m][j][0]+bA,0.f), fmaxf(acc[m][j][1]+bA,0.f));
            *(float2*)&dst[((size_t)b*OC + ocB)*PP + py*Ww + px] =
                make_float2(fmaxf(acc[m][j][2]+bB,0.f), fmaxf(acc[m][j][3]+bB,0.f));
        }
    }
}

// ================================================================================
// K6: a = a3w @ g_a2 + a3b ; weight = sigmoid(a) ; out = relu(x * weight)
// ================================================================================
__global__ __launch_bounds__(256)
void k_final(const float* __restrict__ x, const float* __restrict__ a3w,
             const float* __restrict__ a3b, float* __restrict__ out) {
    int idx = blockIdx.x * 256 + threadIdx.x;       // 65536 float4 groups
    int b  = idx >> 14;
    int p4 = (idx & 16383) * 4;
    float4 acc = make_float4(0.f, 0.f, 0.f, 0.f);
    #pragma unroll 8
    for (int ic = 0; ic < 32; ic++) {
        float wv = a3w[ic];
        float4 v = *(const float4*)&g_a2[((size_t)b*32 + ic)*PP + p4];
        acc.x = fmaf(wv, v.x, acc.x);
        acc.y = fmaf(wv, v.y, acc.y);
        acc.z = fmaf(wv, v.z, acc.z);
        acc.w = fmaf(wv, v.w, acc.w);
    }
    float bb = a3b[0];
    float4 wt;
    wt.x = 1.f / (1.f + expf(-(acc.x + bb)));
    wt.y = 1.f / (1.f + expf(-(acc.y + bb)));
    wt.z = 1.f / (1.f + expf(-(acc.z + bb)));
    wt.w = 1.f / (1.f + expf(-(acc.w + bb)));
    #pragma unroll 4
    for (int c = 0; c < 64; c++) {
        float4 xv = *(const float4*)&x[((size_t)b*64 + c)*PP + p4];
        float4 o;
        o.x = fmaxf(xv.x * wt.x, 0.f);
        o.y = fmaxf(xv.y * wt.y, 0.f);
        o.z = fmaxf(xv.z * wt.z, 0.f);
        o.w = fmaxf(xv.w * wt.w, 0.f);
        *(float4*)&out[((size_t)b*64 + c)*PP + p4] = o;
    }
}

// ================================================================================
extern "C" void kernel_launch(void* const* d_in, const int* in_sizes, int n_in,
                              void* d_out, int out_size) {
    const float* x       = (const float*)d_in[0];
    const float* w_in    = (const float*)d_in[1];
    const float* w_up    = (const float*)d_in[2];
    const float* b_up    = (const float*)d_in[3];
    const float* w_right = (const float*)d_in[4];
    const float* b_right = (const float*)d_in[5];
    const float* w_down  = (const float*)d_in[6];
    const float* b_down  = (const float*)d_in[7];
    const float* w_left  = (const float*)d_in[8];
    const float* b_left  = (const float*)d_in[9];
    const float* wD2     = (const float*)d_in[10];
    const float* a1w     = (const float*)d_in[11];
    const float* a1b     = (const float*)d_in[12];
    const float* a2w     = (const float*)d_in[13];
    const float* a2b     = (const float*)d_in[14];
    const float* a3w     = (const float*)d_in[15];
    const float* a3b     = (const float*)d_in[16];
    float* out = (float*)d_out;

    k_prep<<<188, 256>>>(w_in, wD2, a1w, a2w);
    k_conv_in<<<2048, 128>>>(x);
    dim3 gscan(Bb*Cc, 2);
    k_scan_v<<<gscan, 256>>>(w_up, b_up, w_down, b_down);
    k_scan_h<<<gscan, 256>>>(w_right, b_right, w_left, b_left);
    k_convD2<<<2048, 128>>>();
    k_conv3<64, 0><<<1024, 128>>>(a1b);
    k_conv3<32, 1><<<1024, 128>>>(a2b);
    k_final<<<256, 256>>>(x, a3w, a3b, out);
}

// round 9
// speedup vs baseline: 4.7329x; 1.7139x over previous
#include <cuda_runtime.h>
#include <cuda_fp16.h>
#include <math.h>

#define Bb 4
#define Cc 64
#define Hh 256
#define Ww 256
#define PP (Hh*Ww)          // 65536
#define CH 32

// ---------------- scratch (device globals; fp16 intermediates) -----------------
__device__ __half g_t0h[Bb*Cc*PP];        // conv1x1-in output
__device__ __half g_dirh[4][Bb*Cc*PP];    // 0=up 1=right 2=down 3=left
__device__ __half g_t2h[Bb*Cc*PP];        // wD2 conv output
__device__ __half g_a1h[Bb*CH*PP];
__device__ __half g_a2h[Bb*CH*PP];
// half2 k-pair-packed weights (filled by k_prep each launch)
__device__ __half2 g_win2[32*64];         // [k2*64+oc] = (w_in[oc][2k2], [2k2+1])
__device__ __half2 g_wD22[4*32*64];       // [d][k2*64+oc]
__device__ __half2 g_w3h0[32*9*32];       // [(ic2*9+tap)*32+oc]
__device__ __half2 g_w3h1[16*9*32];

// ---------------- fp16 mma m16n8k16, fp32 accumulate ---------------------------
__device__ __forceinline__ void mma_f16(float* c, const unsigned* a, const unsigned* b) {
    asm volatile("mma.sync.aligned.m16n8k16.row.col.f32.f16.f16.f32 "
        "{%0,%1,%2,%3}, {%4,%5,%6,%7}, {%8,%9}, {%0,%1,%2,%3};"
        : "+f"(c[0]), "+f"(c[1]), "+f"(c[2]), "+f"(c[3])
        : "r"(a[0]), "r"(a[1]), "r"(a[2]), "r"(a[3]), "r"(b[0]), "r"(b[1]));
}
__device__ __forceinline__ unsigned h2u(__half2 h) { return *reinterpret_cast<unsigned*>(&h); }

// ================================================================================
// K0: weight transpose + half2 k-pair packing. 24064 items.
// ================================================================================
__global__ __launch_bounds__(256)
void k_prep(const float* __restrict__ w_in, const float* __restrict__ wD2,
            const float* __restrict__ a1w, const float* __restrict__ a2w) {
    int idx = blockIdx.x * 256 + threadIdx.x;
    if (idx < 2048) {                                   // win2
        int k2 = idx >> 6, oc = idx & 63;
        g_win2[idx] = __floats2half2_rn(w_in[oc*64 + 2*k2], w_in[oc*64 + 2*k2 + 1]);
        return;
    }
    idx -= 2048;
    if (idx < 4*2048) {                                 // wD22
        int d = idx >> 11, r = idx & 2047;
        int k2 = r >> 6, oc = r & 63;
        g_wD22[idx] = __floats2half2_rn(wD2[oc*256 + d*64 + 2*k2],
                                        wD2[oc*256 + d*64 + 2*k2 + 1]);
        return;
    }
    idx -= 4*2048;
    if (idx < 32*9*32) {                                // w3h0 (IC=64 -> 32 pairs)
        int oc = idx & 31, tap = (idx >> 5) % 9, ic2 = idx / (9*32);
        g_w3h0[idx] = __floats2half2_rn(a1w[(oc*64 + 2*ic2)*9 + tap],
                                        a1w[(oc*64 + 2*ic2 + 1)*9 + tap]);
        return;
    }
    idx -= 32*9*32;
    if (idx < 16*9*32) {                                // w3h1 (IC=32 -> 16 pairs)
        int oc = idx & 31, tap = (idx >> 5) % 9, ic2 = idx / (9*32);
        g_w3h1[idx] = __floats2half2_rn(a2w[(oc*32 + 2*ic2)*9 + tap],
                                        a2w[(oc*32 + 2*ic2 + 1)*9 + tap]);
    }
}

// ================================================================================
// K1: g_t0 = w_in @ x via fp16 mma. 128 thr / 4 warps, tile 64oc x 128px, K=64.
// smem: ws2s[k2][oc] pad 72 (bank = 8lc+lr), xs2s[k2][px] pad 136 (bank = 8lc+lr+8j)
// ================================================================================
__global__ __launch_bounds__(128)
void k_conv_in(const float* __restrict__ x) {
    __shared__ __align__(16) __half2 ws2s[32][72];
    __shared__ __align__(16) __half2 xs2s[32][136];
    int tid  = threadIdx.x;
    int lane = tid & 31, warp = tid >> 5;
    int lr = lane >> 2, lc = lane & 3;
    int blk = blockIdx.x;                 // 2048
    int b   = blk >> 9;
    int p0g = (blk & 511) * 128;
    int oc0 = warp * 16;

    for (int t = tid; t < 2048; t += 128) {
        int k2 = t >> 6, oc = t & 63;
        ws2s[k2][oc] = g_win2[t];
    }
    const float* src = x + (size_t)b*64*PP + p0g;
    for (int t = tid; t < 1024; t += 128) {
        int k2 = t >> 5, px4 = (t & 31) * 4;
        float4 v0 = *(const float4*)&src[(size_t)(2*k2)*PP + px4];
        float4 v1 = *(const float4*)&src[(size_t)(2*k2+1)*PP + px4];
        __half2 tmp[4];
        tmp[0] = __floats2half2_rn(v0.x, v1.x);
        tmp[1] = __floats2half2_rn(v0.y, v1.y);
        tmp[2] = __floats2half2_rn(v0.z, v1.z);
        tmp[3] = __floats2half2_rn(v0.w, v1.w);
        *(uint4*)&xs2s[k2][px4] = *(uint4*)tmp;
    }
    __syncthreads();

    float acc[16][4];
    #pragma unroll
    for (int j = 0; j < 16; j++) { acc[j][0]=0.f; acc[j][1]=0.f; acc[j][2]=0.f; acc[j][3]=0.f; }

    #pragma unroll
    for (int kk = 0; kk < 4; kk++) {
        unsigned a[4];
        a[0] = h2u(ws2s[8*kk+lc]  [oc0+lr]);
        a[1] = h2u(ws2s[8*kk+lc]  [oc0+lr+8]);
        a[2] = h2u(ws2s[8*kk+lc+4][oc0+lr]);
        a[3] = h2u(ws2s[8*kk+lc+4][oc0+lr+8]);
        #pragma unroll
        for (int j = 0; j < 16; j++) {
            unsigned bfr[2];
            bfr[0] = h2u(xs2s[8*kk+lc]  [8*j+lr]);
            bfr[1] = h2u(xs2s[8*kk+lc+4][8*j+lr]);
            mma_f16(acc[j], a, bfr);
        }
    }
    __half* dst = g_t0h + (size_t)b*64*PP + p0g;
    #pragma unroll
    for (int j = 0; j < 16; j++) {
        int px = 8*j + 2*lc;
        *(__half2*)&dst[(size_t)(oc0+lr)*PP + px]   = __floats2half2_rn(acc[j][0], acc[j][1]);
        *(__half2*)&dst[(size_t)(oc0+lr+8)*PP + px] = __floats2half2_rn(acc[j][2], acc[j][3]);
    }
}

// ================================================================================
// K2v: vertical IRNN scans, fp32 recurrence over fp16 I/O.
// ================================================================================
__global__ __launch_bounds__(256)
void k_scan_v(const float* __restrict__ w_up, const float* __restrict__ b_up,
              const float* __restrict__ w_down, const float* __restrict__ b_down) {
    int bc = blockIdx.x;
    int c  = bc & 63;
    int up = blockIdx.y;
    int w  = threadIdx.x;
    const __half* src = g_t0h + (size_t)bc*PP;
    __half* dst = (up ? g_dirh[0] : g_dirh[2]) + (size_t)bc*PP;
    float wc = up ? w_up[c] : w_down[c];
    float bv = up ? b_up[c] : b_down[c];
    float h = 0.f;
    if (!up) {
        float v = __half2float(src[w]);
        #pragma unroll 4
        for (int y = 0; y < Hh; y++) {
            float vn = (y < Hh-1) ? __half2float(src[(y+1)*Ww + w]) : 0.f;
            h = fmaxf(fmaf(wc, h, v + bv), 0.f);
            dst[y*Ww + w] = __float2half_rn(h);
            v = vn;
        }
    } else {
        float v = __half2float(src[(Hh-1)*Ww + w]);
        #pragma unroll 4
        for (int y = Hh-1; y >= 0; y--) {
            float vn = (y > 0) ? __half2float(src[(y-1)*Ww + w]) : 0.f;
            h = fmaxf(fmaf(wc, h, v + bv), 0.f);
            dst[y*Ww + w] = __float2half_rn(h);
            v = vn;
        }
    }
}

// ================================================================================
// K2h: horizontal IRNN scans via warp-owned 32x32 smem transpose tiles (fp16 I/O).
// ================================================================================
__global__ __launch_bounds__(256)
void k_scan_h(const float* __restrict__ w_right, const float* __restrict__ b_right,
              const float* __restrict__ w_left, const float* __restrict__ b_left) {
    __shared__ float s[8][32][33];
    int bc = blockIdx.x;
    int c  = bc & 63;
    int lft = blockIdx.y;
    int lane = threadIdx.x & 31, warp = threadIdx.x >> 5;
    const __half* src = g_t0h + (size_t)bc*PP;
    __half* dst = (lft ? g_dirh[3] : g_dirh[1]) + (size_t)bc*PP;
    float wc = lft ? w_left[c] : w_right[c];
    float bv = lft ? b_left[c] : b_right[c];
    int row0 = warp * 32;
    float h = 0.f;
    for (int ch = 0; ch < 8; ch++) {
        int c0 = lft ? (224 - ch*32) : ch*32;
        #pragma unroll
        for (int r = 0; r < 32; r++)
            s[warp][r][lane] = __half2float(src[(row0 + r)*Ww + c0 + lane]);
        __syncwarp();
        if (!lft) {
            #pragma unroll
            for (int j = 0; j < 32; j++) {
                float v = s[warp][lane][j];
                h = fmaxf(fmaf(wc, h, v + bv), 0.f);
                s[warp][lane][j] = h;
            }
        } else {
            #pragma unroll
            for (int j = 31; j >= 0; j--) {
                float v = s[warp][lane][j];
                h = fmaxf(fmaf(wc, h, v + bv), 0.f);
                s[warp][lane][j] = h;
            }
        }
        __syncwarp();
        #pragma unroll
        for (int r = 0; r < 32; r++)
            dst[(row0 + r)*Ww + c0 + lane] = __float2half_rn(s[warp][r][lane]);
        __syncwarp();
    }
}

// ================================================================================
// K3: g_t2 = relu(wD2 @ cat) via fp16 mma. Same tiling as K1, 4 direction chunks.
// ================================================================================
__global__ __launch_bounds__(128)
void k_convD2() {
    __shared__ __align__(16) __half2 ws2s[32][72];
    __shared__ __align__(16) __half2 xs2s[32][136];
    int tid  = threadIdx.x;
    int lane = tid & 31, warp = tid >> 5;
    int lr = lane >> 2, lc = lane & 3;
    int blk = blockIdx.x;                 // 2048
    int b   = blk >> 9;
    int p0g = (blk & 511) * 128;
    int oc0 = warp * 16;

    float acc[16][4];
    #pragma unroll
    for (int j = 0; j < 16; j++) { acc[j][0]=0.f; acc[j][1]=0.f; acc[j][2]=0.f; acc[j][3]=0.f; }

    for (int d = 0; d < 4; d++) {
        __syncthreads();
        const __half2* wsrc = g_wD22 + d*2048;
        for (int t = tid; t < 2048; t += 128) {
            int k2 = t >> 6, oc = t & 63;
            ws2s[k2][oc] = wsrc[t];
        }
        const __half* srcd = (const __half*)g_dirh[d] + (size_t)b*64*PP + p0g;
        for (int t = tid; t < 1024; t += 128) {
            int k2 = t >> 5, px4 = (t & 31) * 4;
            __half2 r0a = *(const __half2*)&srcd[(size_t)(2*k2)*PP + px4];
            __half2 r0b = *(const __half2*)&srcd[(size_t)(2*k2)*PP + px4 + 2];
            __half2 r1a = *(const __half2*)&srcd[(size_t)(2*k2+1)*PP + px4];
            __half2 r1b = *(const __half2*)&srcd[(size_t)(2*k2+1)*PP + px4 + 2];
            __half2 tmp[4];
            tmp[0] = __halves2half2(__low2half(r0a),  __low2half(r1a));
            tmp[1] = __halves2half2(__high2half(r0a), __high2half(r1a));
            tmp[2] = __halves2half2(__low2half(r0b),  __low2half(r1b));
            tmp[3] = __halves2half2(__high2half(r0b), __high2half(r1b));
            *(uint4*)&xs2s[k2][px4] = *(uint4*)tmp;
        }
        __syncthreads();
        #pragma unroll
        for (int kk = 0; kk < 4; kk++) {
            unsigned a[4];
            a[0] = h2u(ws2s[8*kk+lc]  [oc0+lr]);
            a[1] = h2u(ws2s[8*kk+lc]  [oc0+lr+8]);
            a[2] = h2u(ws2s[8*kk+lc+4][oc0+lr]);
            a[3] = h2u(ws2s[8*kk+lc+4][oc0+lr+8]);
            #pragma unroll
            for (int j = 0; j < 16; j++) {
                unsigned bfr[2];
                bfr[0] = h2u(xs2s[8*kk+lc]  [8*j+lr]);
                bfr[1] = h2u(xs2s[8*kk+lc+4][8*j+lr]);
                mma_f16(acc[j], a, bfr);
            }
        }
    }
    __half* dst = g_t2h + (size_t)b*64*PP + p0g;
    #pragma unroll
    for (int j = 0; j < 16; j++) {
        int px = 8*j + 2*lc;
        *(__half2*)&dst[(size_t)(oc0+lr)*PP + px] =
            __floats2half2_rn(fmaxf(acc[j][0],0.f), fmaxf(acc[j][1],0.f));
        *(__half2*)&dst[(size_t)(oc0+lr+8)*PP + px] =
            __floats2half2_rn(fmaxf(acc[j][2],0.f), fmaxf(acc[j][3],0.f));
    }
}

// ================================================================================
// K4/K5: conv3x3 SAME + relu via fp16 mma (implicit GEMM over taps).
// 128 thr / 4 warps. Out tile 32oc x (32x by 8y). K per stage = 16 ic (one k16 mma
// per tap). wsm2[tap][icl2][40] (bank 8lc+lr), in_s2[icl2][10][36] half2 ic-pairs.
// ================================================================================
template<int IC, int LAYER>
__global__ __launch_bounds__(128)
void k_conv3(const float* __restrict__ bias) {
    constexpr int OC = 32;
    __shared__ __align__(16) __half2 wsm2[9][8][40];
    __shared__ __align__(16) __half2 in_s2[8][10][36];

    const __half* src = (LAYER == 0) ? g_t2h : g_a1h;
    __half*       dst = (LAYER == 0) ? g_a1h : g_a2h;
    const __half2* wT = (LAYER == 0) ? g_w3h0 : g_w3h1;

    int tid  = threadIdx.x;
    int lane = tid & 31, warp = tid >> 5;
    int lr = lane >> 2, lc = lane & 3;
    int blk = blockIdx.x;                              // 1024
    int b   = blk >> 8;
    int t   = blk & 255;
    int ty0 = (t >> 3) * 8;
    int tx0 = (t & 7) * 32;
    const __half* sb = src + (size_t)b*IC*PP;

    float acc[2][8][4];
    #pragma unroll
    for (int m = 0; m < 2; m++)
        #pragma unroll
        for (int j = 0; j < 8; j++)
            { acc[m][j][0]=0.f; acc[m][j][1]=0.f; acc[m][j][2]=0.f; acc[m][j][3]=0.f; }

    for (int ic20 = 0; ic20 < IC/2; ic20 += 8) {       // 16 ic per stage
        __syncthreads();
        for (int tt = tid; tt < 8*9*32; tt += 128) {
            int oc = tt & 31;
            int q  = tt >> 5;                          // icl2*9 + tap (source order)
            int tap = q % 9, icl2 = q / 9;
            wsm2[tap][icl2][oc] = wT[((ic20 + icl2)*9 + tap)*32 + oc];
        }
        for (int tt = tid; tt < 8*10*34; tt += 128) {
            int col = tt % 34;
            int rr  = (tt / 34) % 10;
            int icl2 = tt / 340;
            int gy = ty0 + rr - 1, gx = tx0 + col - 1;
            __half2 v = __floats2half2_rn(0.f, 0.f);
            if (gy >= 0 && gy < Hh && gx >= 0 && gx < Ww) {
                size_t off = (size_t)(2*(ic20 + icl2))*PP + gy*Ww + gx;
                v = __halves2half2(sb[off], sb[off + PP]);
            }
            in_s2[icl2][rr][col] = v;
        }
        __syncthreads();

        #pragma unroll
        for (int tap = 0; tap < 9; tap++) {
            int dy = tap / 3, dx = tap % 3;
            unsigned aA[4], aB[4];
            aA[0] = h2u(wsm2[tap][lc]  [lr]);
            aA[1] = h2u(wsm2[tap][lc]  [lr+8]);
            aA[2] = h2u(wsm2[tap][lc+4][lr]);
            aA[3] = h2u(wsm2[tap][lc+4][lr+8]);
            aB[0] = h2u(wsm2[tap][lc]  [lr+16]);
            aB[1] = h2u(wsm2[tap][lc]  [lr+24]);
            aB[2] = h2u(wsm2[tap][lc+4][lr+16]);
            aB[3] = h2u(wsm2[tap][lc+4][lr+24]);
            #pragma unroll
            for (int j = 0; j < 8; j++) {
                int y = 2*warp + (j >> 2);
                int x = 8*(j & 3) + lr;
                unsigned bfr[2];
                bfr[0] = h2u(in_s2[lc]  [y+dy][x+dx]);
                bfr[1] = h2u(in_s2[lc+4][y+dy][x+dx]);
                mma_f16(acc[0][j], aA, bfr);
                mma_f16(acc[1][j], aB, bfr);
            }
        }
    }
    #pragma unroll
    for (int m = 0; m < 2; m++) {
        int ocA = 16*m + lr, ocB = 16*m + lr + 8;
        float bA = bias[ocA], bB = bias[ocB];
        #pragma unroll
        for (int j = 0; j < 8; j++) {
            int py = ty0 + 2*warp + (j >> 2);
            int px = tx0 + 8*(j & 3) + 2*lc;
            *(__half2*)&dst[((size_t)b*OC + ocA)*PP + py*Ww + px] =
                __floats2half2_rn(fmaxf(acc[m][j][0]+bA,0.f), fmaxf(acc[m][j][1]+bA,0.f));
            *(__half2*)&dst[((size_t)b*OC + ocB)*PP + py*Ww + px] =
                __floats2half2_rn(fmaxf(acc[m][j][2]+bB,0.f), fmaxf(acc[m][j][3]+bB,0.f));
        }
    }
}

// ================================================================================
// K6: a = a3w @ g_a2 + a3b ; weight = sigmoid(a) ; out = relu(x * weight)
// ================================================================================
__global__ __launch_bounds__(256)
void k_final(const float* __restrict__ x, const float* __restrict__ a3w,
             const float* __restrict__ a3b, float* __restrict__ out) {
    int idx = blockIdx.x * 256 + threadIdx.x;       // 65536 float4 groups
    int b  = idx >> 14;
    int p4 = (idx & 16383) * 4;
    float4 acc = make_float4(0.f, 0.f, 0.f, 0.f);
    #pragma unroll 8
    for (int ic = 0; ic < 32; ic++) {
        float wv = a3w[ic];
        const __half2* p = (const __half2*)&g_a2h[((size_t)b*32 + ic)*PP + p4];
        float2 f01 = __half22float2(p[0]);
        float2 f23 = __half22float2(p[1]);
        acc.x = fmaf(wv, f01.x, acc.x);
        acc.y = fmaf(wv, f01.y, acc.y);
        acc.z = fmaf(wv, f23.x, acc.z);
        acc.w = fmaf(wv, f23.y, acc.w);
    }
    float bb = a3b[0];
    float4 wt;
    wt.x = 1.f / (1.f + expf(-(acc.x + bb)));
    wt.y = 1.f / (1.f + expf(-(acc.y + bb)));
    wt.z = 1.f / (1.f + expf(-(acc.z + bb)));
    wt.w = 1.f / (1.f + expf(-(acc.w + bb)));
    #pragma unroll 4
    for (int c = 0; c < 64; c++) {
        float4 xv = *(const float4*)&x[((size_t)b*64 + c)*PP + p4];
        float4 o;
        o.x = fmaxf(xv.x * wt.x, 0.f);
        o.y = fmaxf(xv.y * wt.y, 0.f);
        o.z = fmaxf(xv.z * wt.z, 0.f);
        o.w = fmaxf(xv.w * wt.w, 0.f);
        *(float4*)&out[((size_t)b*64 + c)*PP + p4] = o;
    }
}

// ================================================================================
extern "C" void kernel_launch(void* const* d_in, const int* in_sizes, int n_in,
                              void* d_out, int out_size) {
    const float* x       = (const float*)d_in[0];
    const float* w_in    = (const float*)d_in[1];
    const float* w_up    = (const float*)d_in[2];
    const float* b_up    = (const float*)d_in[3];
    const float* w_right = (const float*)d_in[4];
    const float* b_right = (const float*)d_in[5];
    const float* w_down  = (const float*)d_in[6];
    const float* b_down  = (const float*)d_in[7];
    const float* w_left  = (const float*)d_in[8];
    const float* b_left  = (const float*)d_in[9];
    const float* wD2     = (const float*)d_in[10];
    const float* a1w     = (const float*)d_in[11];
    const float* a1b     = (const float*)d_in[12];
    const float* a2w     = (const float*)d_in[13];
    const float* a2b     = (const float*)d_in[14];
    const float* a3w     = (const float*)d_in[15];
    const float* a3b     = (const float*)d_in[16];
    float* out = (float*)d_out;

    k_prep<<<94, 256>>>(w_in, wD2, a1w, a2w);
    k_conv_in<<<2048, 128>>>(x);
    dim3 gscan(Bb*Cc, 2);
    k_scan_v<<<gscan, 256>>>(w_up, b_up, w_down, b_down);
    k_scan_h<<<gscan, 256>>>(w_right, b_right, w_left, b_left);
    k_convD2<<<2048, 128>>>();
    k_conv3<64, 0><<<1024, 128>>>(a1b);
    k_conv3<32, 1><<<1024, 128>>>(a2b);
    k_final<<<256, 256>>>(x, a3w, a3b, out);
}

// round 10
// speedup vs baseline: 5.1035x; 1.0783x over previous
#include <cuda_runtime.h>
#include <cuda_fp16.h>
#include <math.h>

#define Bb 4
#define Cc 64
#define Hh 256
#define Ww 256
#define PP (Hh*Ww)          // 65536
#define CH 32

// ---------------- scratch: channel-pair interleaved fp16 -----------------------
// buf[(c>>1)*PP + px] = half2(ch_even[px], ch_odd[px])
__device__ __half2 g_t02[Bb*32*PP];
__device__ __half2 g_dir2[4][Bb*32*PP];   // 0=up 1=right 2=down 3=left
__device__ __half2 g_t22[Bb*32*PP];
__device__ __half2 g_a12[Bb*16*PP];
__device__ __half2 g_a22[Bb*16*PP];
// half2 k-pair-packed weights
__device__ __half2 g_win2[32*64];         // [k2*64+oc]
__device__ __half2 g_wD22[4*32*64];       // [d][k2*64+oc]
__device__ __half2 g_w3h0[32*9*32];       // [(ic2*9+tap)*32+oc]
__device__ __half2 g_w3h1[16*9*32];

// ---------------- fp16 mma m16n8k16, fp32 accumulate ---------------------------
__device__ __forceinline__ void mma_f16(float* c, const unsigned* a, const unsigned* b) {
    asm volatile("mma.sync.aligned.m16n8k16.row.col.f32.f16.f16.f32 "
        "{%0,%1,%2,%3}, {%4,%5,%6,%7}, {%8,%9}, {%0,%1,%2,%3};"
        : "+f"(c[0]), "+f"(c[1]), "+f"(c[2]), "+f"(c[3])
        : "r"(a[0]), "r"(a[1]), "r"(a[2]), "r"(a[3]), "r"(b[0]), "r"(b[1]));
}
__device__ __forceinline__ unsigned h2u(__half2 h) { return *reinterpret_cast<unsigned*>(&h); }
__device__ __forceinline__ unsigned packh2(float a, float b) {
    __half2 t = __floats2half2_rn(a, b);
    return *reinterpret_cast<unsigned*>(&t);
}

// Pair-interleave epilogue: thread (lr,lc) holds D rows (r0=lr, r0+8) at px pair
// (2lc, 2lc+1) as u01 (row lr) / u23 (row lr+8). shfl-bfly(4) exchanges lr^1.
// Even lr writes pair rows (lr, lr+1) [from u01], odd lr writes (lr+7+8.. i.e.
// rows (lr-1+8, lr+8)) [from u23]. Returns packed uint2 = half2 at px, px+1.
__device__ __forceinline__ uint2 pair_merge(unsigned u01, unsigned u23, bool even) {
    unsigned r01 = __shfl_xor_sync(0xffffffffu, u01, 4);
    unsigned r23 = __shfl_xor_sync(0xffffffffu, u23, 4);
    unsigned a = even ? u01 : r23;      // even-numbered oc row of the pair
    unsigned b = even ? r01 : u23;      // odd-numbered oc row
    return make_uint2(__byte_perm(a, b, 0x5410), __byte_perm(a, b, 0x7632));
}

// ================================================================================
// K0: weight transpose + half2 k-pair packing.
// ================================================================================
__global__ __launch_bounds__(256)
void k_prep(const float* __restrict__ w_in, const float* __restrict__ wD2,
            const float* __restrict__ a1w, const float* __restrict__ a2w) {
    int idx = blockIdx.x * 256 + threadIdx.x;
    if (idx < 2048) {
        int k2 = idx >> 6, oc = idx & 63;
        g_win2[idx] = __floats2half2_rn(w_in[oc*64 + 2*k2], w_in[oc*64 + 2*k2 + 1]);
        return;
    }
    idx -= 2048;
    if (idx < 4*2048) {
        int d = idx >> 11, r = idx & 2047;
        int k2 = r >> 6, oc = r & 63;
        g_wD22[idx] = __floats2half2_rn(wD2[oc*256 + d*64 + 2*k2],
                                        wD2[oc*256 + d*64 + 2*k2 + 1]);
        return;
    }
    idx -= 4*2048;
    if (idx < 32*9*32) {
        int oc = idx & 31, tap = (idx >> 5) % 9, ic2 = idx / (9*32);
        g_w3h0[idx] = __floats2half2_rn(a1w[(oc*64 + 2*ic2)*9 + tap],
                                        a1w[(oc*64 + 2*ic2 + 1)*9 + tap]);
        return;
    }
    idx -= 32*9*32;
    if (idx < 16*9*32) {
        int oc = idx & 31, tap = (idx >> 5) % 9, ic2 = idx / (9*32);
        g_w3h1[idx] = __floats2half2_rn(a2w[(oc*32 + 2*ic2)*9 + tap],
                                        a2w[(oc*32 + 2*ic2 + 1)*9 + tap]);
    }
}

// ================================================================================
// K1: t0 = w_in @ x. 128 thr/4 warps, tile 64oc x 128px, K=64. Interleaved output.
// ================================================================================
__global__ __launch_bounds__(128)
void k_conv_in(const float* __restrict__ x) {
    __shared__ __align__(16) __half2 ws2s[32][72];
    __shared__ __align__(16) __half2 xs2s[32][136];
    int tid  = threadIdx.x;
    int lane = tid & 31, warp = tid >> 5;
    int lr = lane >> 2, lc = lane & 3;
    int blk = blockIdx.x;                 // 2048
    int b   = blk >> 9;
    int p0g = (blk & 511) * 128;
    int oc0 = warp * 16;

    for (int t = tid; t < 2048; t += 128) {
        int k2 = t >> 6, oc = t & 63;
        ws2s[k2][oc] = g_win2[t];
    }
    const float* src = x + (size_t)b*64*PP + p0g;
    for (int t = tid; t < 1024; t += 128) {
        int k2 = t >> 5, px4 = (t & 31) * 4;
        float4 v0 = *(const float4*)&src[(size_t)(2*k2)*PP + px4];
        float4 v1 = *(const float4*)&src[(size_t)(2*k2+1)*PP + px4];
        __half2 tmp[4];
        tmp[0] = __floats2half2_rn(v0.x, v1.x);
        tmp[1] = __floats2half2_rn(v0.y, v1.y);
        tmp[2] = __floats2half2_rn(v0.z, v1.z);
        tmp[3] = __floats2half2_rn(v0.w, v1.w);
        *(uint4*)&xs2s[k2][px4] = *(uint4*)tmp;
    }
    __syncthreads();

    float acc[16][4];
    #pragma unroll
    for (int j = 0; j < 16; j++) { acc[j][0]=0.f; acc[j][1]=0.f; acc[j][2]=0.f; acc[j][3]=0.f; }

    #pragma unroll
    for (int kk = 0; kk < 4; kk++) {
        unsigned a[4];
        a[0] = h2u(ws2s[8*kk+lc]  [oc0+lr]);
        a[1] = h2u(ws2s[8*kk+lc]  [oc0+lr+8]);
        a[2] = h2u(ws2s[8*kk+lc+4][oc0+lr]);
        a[3] = h2u(ws2s[8*kk+lc+4][oc0+lr+8]);
        #pragma unroll
        for (int j = 0; j < 16; j++) {
            unsigned bfr[2];
            bfr[0] = h2u(xs2s[8*kk+lc]  [8*j+lr]);
            bfr[1] = h2u(xs2s[8*kk+lc+4][8*j+lr]);
            mma_f16(acc[j], a, bfr);
        }
    }
    __half2* dst2 = g_t02 + (size_t)b*32*PP + p0g;
    bool even = (lr & 1) == 0;
    int m = even ? (lr >> 1) : ((lr - 1) >> 1);
    int oc2 = 8*warp + (even ? m : 4 + m);
    #pragma unroll
    for (int j = 0; j < 16; j++) {
        unsigned u01 = packh2(acc[j][0], acc[j][1]);
        unsigned u23 = packh2(acc[j][2], acc[j][3]);
        uint2 v = pair_merge(u01, u23, even);
        *(uint2*)&dst2[(size_t)oc2*PP + 8*j + 2*lc] = v;
    }
}

// ================================================================================
// K2v: vertical IRNN scans, 2 channels/thread via half2. grid (128,2,2), 128 thr.
// ================================================================================
__global__ __launch_bounds__(128)
void k_scan_v(const float* __restrict__ w_up, const float* __restrict__ b_up,
              const float* __restrict__ w_down, const float* __restrict__ b_down) {
    int plane = blockIdx.x;               // b*32 + k2
    int up    = blockIdx.y;
    int w     = blockIdx.z * 128 + threadIdx.x;
    int k2    = plane & 31;
    const __half2* src = g_t02 + (size_t)plane*PP;
    __half2* dst = (up ? g_dir2[0] : g_dir2[2]) + (size_t)plane*PP;
    float wc0 = up ? w_up[2*k2]   : w_down[2*k2];
    float wc1 = up ? w_up[2*k2+1] : w_down[2*k2+1];
    float bv0 = up ? b_up[2*k2]   : b_down[2*k2];
    float bv1 = up ? b_up[2*k2+1] : b_down[2*k2+1];
    float h0 = 0.f, h1 = 0.f;
    if (!up) {
        float2 v = __half22float2(src[w]);
        #pragma unroll 4
        for (int y = 0; y < Hh; y++) {
            float2 vn = (y < Hh-1) ? __half22float2(src[(y+1)*Ww + w]) : make_float2(0.f,0.f);
            h0 = fmaxf(fmaf(wc0, h0, v.x + bv0), 0.f);
            h1 = fmaxf(fmaf(wc1, h1, v.y + bv1), 0.f);
            dst[y*Ww + w] = __floats2half2_rn(h0, h1);
            v = vn;
        }
    } else {
        float2 v = __half22float2(src[(Hh-1)*Ww + w]);
        #pragma unroll 4
        for (int y = Hh-1; y >= 0; y--) {
            float2 vn = (y > 0) ? __half22float2(src[(y-1)*Ww + w]) : make_float2(0.f,0.f);
            h0 = fmaxf(fmaf(wc0, h0, v.x + bv0), 0.f);
            h1 = fmaxf(fmaf(wc1, h1, v.y + bv1), 0.f);
            dst[y*Ww + w] = __floats2half2_rn(h0, h1);
            v = vn;
        }
    }
}

// ================================================================================
// K2h: horizontal IRNN scans, half2 transpose tiles, 2 channels/warp-row.
// grid (128,2,2), 128 thr / 4 warps, each warp 32 rows.
// ================================================================================
__global__ __launch_bounds__(128)
void k_scan_h(const float* __restrict__ w_right, const float* __restrict__ b_right,
              const float* __restrict__ w_left, const float* __restrict__ b_left) {
    __shared__ __half2 s[4][32][33];
    int plane = blockIdx.x;
    int lft   = blockIdx.y;
    int k2    = plane & 31;
    int lane = threadIdx.x & 31, warp = threadIdx.x >> 5;
    const __half2* src = g_t02 + (size_t)plane*PP;
    __half2* dst = (lft ? g_dir2[3] : g_dir2[1]) + (size_t)plane*PP;
    float wc0 = lft ? w_left[2*k2]   : w_right[2*k2];
    float wc1 = lft ? w_left[2*k2+1] : w_right[2*k2+1];
    float bv0 = lft ? b_left[2*k2]   : b_right[2*k2];
    float bv1 = lft ? b_left[2*k2+1] : b_right[2*k2+1];
    int row0 = blockIdx.z * 128 + warp * 32;
    float h0 = 0.f, h1 = 0.f;
    for (int ch = 0; ch < 8; ch++) {
        int c0 = lft ? (224 - ch*32) : ch*32;
        #pragma unroll
        for (int r = 0; r < 32; r++)
            s[warp][r][lane] = src[(row0 + r)*Ww + c0 + lane];
        __syncwarp();
        if (!lft) {
            #pragma unroll
            for (int j = 0; j < 32; j++) {
                float2 v = __half22float2(s[warp][lane][j]);
                h0 = fmaxf(fmaf(wc0, h0, v.x + bv0), 0.f);
                h1 = fmaxf(fmaf(wc1, h1, v.y + bv1), 0.f);
                s[warp][lane][j] = __floats2half2_rn(h0, h1);
            }
        } else {
            #pragma unroll
            for (int j = 31; j >= 0; j--) {
                float2 v = __half22float2(s[warp][lane][j]);
                h0 = fmaxf(fmaf(wc0, h0, v.x + bv0), 0.f);
                h1 = fmaxf(fmaf(wc1, h1, v.y + bv1), 0.f);
                s[warp][lane][j] = __floats2half2_rn(h0, h1);
            }
        }
        __syncwarp();
        #pragma unroll
        for (int r = 0; r < 32; r++)
            dst[(row0 + r)*Ww + c0 + lane] = s[warp][r][lane];
        __syncwarp();
    }
}

// ================================================================================
// K3: t2 = relu(wD2 @ cat). Staging from interleaved dir = pure uint4 copies.
// ================================================================================
__global__ __launch_bounds__(128)
void k_convD2() {
    __shared__ __align__(16) __half2 ws2s[32][72];
    __shared__ __align__(16) __half2 xs2s[32][136];
    int tid  = threadIdx.x;
    int lane = tid & 31, warp = tid >> 5;
    int lr = lane >> 2, lc = lane & 3;
    int blk = blockIdx.x;                 // 2048
    int b   = blk >> 9;
    int p0g = (blk & 511) * 128;
    int oc0 = warp * 16;

    float acc[16][4];
    #pragma unroll
    for (int j = 0; j < 16; j++) { acc[j][0]=0.f; acc[j][1]=0.f; acc[j][2]=0.f; acc[j][3]=0.f; }

    for (int d = 0; d < 4; d++) {
        __syncthreads();
        const __half2* wsrc = g_wD22 + d*2048;
        for (int t = tid; t < 2048; t += 128) {
            int k2 = t >> 6, oc = t & 63;
            ws2s[k2][oc] = wsrc[t];
        }
        const __half2* srcd = (const __half2*)g_dir2[d] + (size_t)b*32*PP + p0g;
        for (int t = tid; t < 1024; t += 128) {
            int k2 = t >> 5, px4 = (t & 31) * 4;
            *(uint4*)&xs2s[k2][px4] = *(const uint4*)&srcd[(size_t)k2*PP + px4];
        }
        __syncthreads();
        #pragma unroll
        for (int kk = 0; kk < 4; kk++) {
            unsigned a[4];
            a[0] = h2u(ws2s[8*kk+lc]  [oc0+lr]);
            a[1] = h2u(ws2s[8*kk+lc]  [oc0+lr+8]);
            a[2] = h2u(ws2s[8*kk+lc+4][oc0+lr]);
            a[3] = h2u(ws2s[8*kk+lc+4][oc0+lr+8]);
            #pragma unroll
            for (int j = 0; j < 16; j++) {
                unsigned bfr[2];
                bfr[0] = h2u(xs2s[8*kk+lc]  [8*j+lr]);
                bfr[1] = h2u(xs2s[8*kk+lc+4][8*j+lr]);
                mma_f16(acc[j], a, bfr);
            }
        }
    }
    __half2* dst2 = g_t22 + (size_t)b*32*PP + p0g;
    bool even = (lr & 1) == 0;
    int m = even ? (lr >> 1) : ((lr - 1) >> 1);
    int oc2 = 8*warp + (even ? m : 4 + m);
    #pragma unroll
    for (int j = 0; j < 16; j++) {
        unsigned u01 = packh2(fmaxf(acc[j][0],0.f), fmaxf(acc[j][1],0.f));
        unsigned u23 = packh2(fmaxf(acc[j][2],0.f), fmaxf(acc[j][3],0.f));
        uint2 v = pair_merge(u01, u23, even);
        *(uint2*)&dst2[(size_t)oc2*PP + 8*j + 2*lc] = v;
    }
}

// ================================================================================
// K4/K5: conv3x3 SAME + relu via fp16 mma. Interleaved src: single half2 loads.
// ================================================================================
template<int IC, int LAYER>
__global__ __launch_bounds__(128)
void k_conv3(const float* __restrict__ bias) {
    __shared__ __align__(16) __half2 wsm2[9][8][40];
    __shared__ __align__(16) __half2 in_s2[8][10][36];

    const __half2* src2 = (LAYER == 0) ? g_t22 : g_a12;
    __half2*       dst2 = (LAYER == 0) ? g_a12 : g_a22;
    const __half2* wT   = (LAYER == 0) ? g_w3h0 : g_w3h1;
    constexpr int ICP = IC/2;

    int tid  = threadIdx.x;
    int lane = tid & 31, warp = tid >> 5;
    int lr = lane >> 2, lc = lane & 3;
    int blk = blockIdx.x;                              // 1024
    int b   = blk >> 8;
    int t   = blk & 255;
    int ty0 = (t >> 3) * 8;
    int tx0 = (t & 7) * 32;
    const __half2* sb = src2 + (size_t)b*ICP*PP;

    float acc[2][8][4];
    #pragma unroll
    for (int m = 0; m < 2; m++)
        #pragma unroll
        for (int j = 0; j < 8; j++)
            { acc[m][j][0]=0.f; acc[m][j][1]=0.f; acc[m][j][2]=0.f; acc[m][j][3]=0.f; }

    for (int ic20 = 0; ic20 < ICP; ic20 += 8) {
        __syncthreads();
        for (int tt = tid; tt < 8*9*32; tt += 128) {
            int oc = tt & 31;
            int q  = tt >> 5;
            int tap = q % 9, icl2 = q / 9;
            wsm2[tap][icl2][oc] = wT[((ic20 + icl2)*9 + tap)*32 + oc];
        }
        for (int tt = tid; tt < 8*10*34; tt += 128) {
            int col = tt % 34;
            int rr  = (tt / 34) % 10;
            int icl2 = tt / 340;
            int gy = ty0 + rr - 1, gx = tx0 + col - 1;
            __half2 v = __floats2half2_rn(0.f, 0.f);
            if (gy >= 0 && gy < Hh && gx >= 0 && gx < Ww)
                v = sb[(size_t)(ic20 + icl2)*PP + gy*Ww + gx];
            in_s2[icl2][rr][col] = v;
        }
        __syncthreads();

        #pragma unroll
        for (int tap = 0; tap < 9; tap++) {
            int dy = tap / 3, dx = tap % 3;
            unsigned aA[4], aB[4];
            aA[0] = h2u(wsm2[tap][lc]  [lr]);
            aA[1] = h2u(wsm2[tap][lc]  [lr+8]);
            aA[2] = h2u(wsm2[tap][lc+4][lr]);
            aA[3] = h2u(wsm2[tap][lc+4][lr+8]);
            aB[0] = h2u(wsm2[tap][lc]  [lr+16]);
            aB[1] = h2u(wsm2[tap][lc]  [lr+24]);
            aB[2] = h2u(wsm2[tap][lc+4][lr+16]);
            aB[3] = h2u(wsm2[tap][lc+4][lr+24]);
            #pragma unroll
            for (int j = 0; j < 8; j++) {
                int y = 2*warp + (j >> 2);
                int x = 8*(j & 3) + lr;
                unsigned bfr[2];
                bfr[0] = h2u(in_s2[lc]  [y+dy][x+dx]);
                bfr[1] = h2u(in_s2[lc+4][y+dy][x+dx]);
                mma_f16(acc[0][j], aA, bfr);
                mma_f16(acc[1][j], aB, bfr);
            }
        }
    }
    bool even = (lr & 1) == 0;
    int q = even ? (lr >> 1) : ((lr - 1) >> 1);
    #pragma unroll
    for (int m = 0; m < 2; m++) {
        int ocA = 16*m + lr, ocB = 16*m + lr + 8;
        float bA = bias[ocA], bB = bias[ocB];
        int oc2 = 8*m + (even ? q : 4 + q);
        #pragma unroll
        for (int j = 0; j < 8; j++) {
            int py = ty0 + 2*warp + (j >> 2);
            int px = tx0 + 8*(j & 3) + 2*lc;
            unsigned u01 = packh2(fmaxf(acc[m][j][0]+bA,0.f), fmaxf(acc[m][j][1]+bA,0.f));
            unsigned u23 = packh2(fmaxf(acc[m][j][2]+bB,0.f), fmaxf(acc[m][j][3]+bB,0.f));
            uint2 v = pair_merge(u01, u23, even);
            *(uint2*)&dst2[((size_t)b*16 + oc2)*PP + py*Ww + px] = v;
        }
    }
}

// ================================================================================
// K6: a = a3w @ a2 + a3b ; weight = sigmoid(a) ; out = relu(x * weight)
// ================================================================================
__global__ __launch_bounds__(256)
void k_final(const float* __restrict__ x, const float* __restrict__ a3w,
             const float* __restrict__ a3b, float* __restrict__ out) {
    int idx = blockIdx.x * 256 + threadIdx.x;       // 65536 groups of 4 px
    int b  = idx >> 14;
    int p4 = (idx & 16383) * 4;
    const __half2* a2 = g_a22 + (size_t)b*16*PP;
    float4 acc = make_float4(0.f, 0.f, 0.f, 0.f);
    #pragma unroll
    for (int ic2 = 0; ic2 < 16; ic2++) {
        float w0 = a3w[2*ic2], w1 = a3w[2*ic2+1];
        uint4 raw = *(const uint4*)&a2[(size_t)ic2*PP + p4];
        __half2* h = (__half2*)&raw;
        float2 f0 = __half22float2(h[0]);
        float2 f1 = __half22float2(h[1]);
        float2 f2 = __half22float2(h[2]);
        float2 f3 = __half22float2(h[3]);
        acc.x += w0*f0.x + w1*f0.y;
        acc.y += w0*f1.x + w1*f1.y;
        acc.z += w0*f2.x + w1*f2.y;
        acc.w += w0*f3.x + w1*f3.y;
    }
    float bb = a3b[0];
    float4 wt;
    wt.x = 1.f / (1.f + expf(-(acc.x + bb)));
    wt.y = 1.f / (1.f + expf(-(acc.y + bb)));
    wt.z = 1.f / (1.f + expf(-(acc.z + bb)));
    wt.w = 1.f / (1.f + expf(-(acc.w + bb)));
    #pragma unroll 4
    for (int c = 0; c < 64; c++) {
        float4 xv = *(const float4*)&x[((size_t)b*64 + c)*PP + p4];
        float4 o;
        o.x = fmaxf(xv.x * wt.x, 0.f);
        o.y = fmaxf(xv.y * wt.y, 0.f);
        o.z = fmaxf(xv.z * wt.z, 0.f);
        o.w = fmaxf(xv.w * wt.w, 0.f);
        *(float4*)&out[((size_t)b*64 + c)*PP + p4] = o;
    }
}

// ================================================================================
extern "C" void kernel_launch(void* const* d_in, const int* in_sizes, int n_in,
                              void* d_out, int out_size) {
    const float* x       = (const float*)d_in[0];
    const float* w_in    = (const float*)d_in[1];
    const float* w_up    = (const float*)d_in[2];
    const float* b_up    = (const float*)d_in[3];
    const float* w_right = (const float*)d_in[4];
    const float* b_right = (const float*)d_in[5];
    const float* w_down  = (const float*)d_in[6];
    const float* b_down  = (const float*)d_in[7];
    const float* w_left  = (const float*)d_in[8];
    const float* b_left  = (const float*)d_in[9];
    const float* wD2     = (const float*)d_in[10];
    const float* a1w     = (const float*)d_in[11];
    const float* a1b     = (const float*)d_in[12];
    const float* a2w     = (const float*)d_in[13];
    const float* a2b     = (const float*)d_in[14];
    const float* a3w     = (const float*)d_in[15];
    const float* a3b     = (const float*)d_in[16];
    float* out = (float*)d_out;

    k_prep<<<94, 256>>>(w_in, wD2, a1w, a2w);
    k_conv_in<<<2048, 128>>>(x);
    dim3 gscan(Bb*32, 2, 2);
    k_scan_v<<<gscan, 128>>>(w_up, b_up, w_down, b_down);
    k_scan_h<<<gscan, 128>>>(w_right, b_right, w_left, b_left);
    k_convD2<<<2048, 128>>>();
    k_conv3<64, 0><<<1024, 128>>>(a1b);
    k_conv3<32, 1><<<1024, 128>>>(a2b);
    k_final<<<256, 256>>>(x, a3w, a3b, out);
}